// round 1
// baseline (speedup 1.0000x reference)
#include <cuda_runtime.h>
#include <cuda_bf16.h>
#include <cstdio>

#define N_NODES 50000
#define N_EDGES 800000
#define DIM_D   128
#define DIM_H   256
#define DIM_A   16

// ---------------- scratch (static device allocations; no cudaMalloc) --------
__device__ float g_bufA[N_NODES * DIM_H];   // 51.2 MB
__device__ float g_bufB[N_NODES * DIM_H];   // 51.2 MB
__device__ float g_P[N_NODES * DIM_H];      // 51.2 MB
__device__ float g_Q[N_NODES * DIM_H];      // 51.2 MB
__device__ float g_norm[N_EDGES];
__device__ float g_dinv[N_NODES];
__device__ int   g_deg[N_NODES];
__device__ int   g_offs[N_NODES + 1];
__device__ int   g_cursor[N_NODES];
__device__ int   g_eidx[N_EDGES];

// ---------------- fp32x2 packed helpers -------------------------------------
__device__ __forceinline__ unsigned long long pk2(float lo, float hi) {
    unsigned long long r;
    asm("mov.b64 %0, {%1,%2};" : "=l"(r) : "f"(lo), "f"(hi));
    return r;
}
__device__ __forceinline__ void fma2(unsigned long long& d, unsigned long long a,
                                     unsigned long long b) {
    asm("fma.rn.f32x2 %0, %1, %2, %3;" : "=l"(d) : "l"(a), "l"(b), "l"(d));
}
__device__ __forceinline__ float2 up2(unsigned long long v) {
    float lo, hi;
    asm("mov.b64 {%0,%1}, %2;" : "=f"(lo), "=f"(hi) : "l"(v));
    return make_float2(lo, hi);
}

// ---------------- small prep kernels ----------------------------------------
__global__ void zero2_kernel(int* a, int* b, int n) {
    int i = blockIdx.x * blockDim.x + threadIdx.x;
    if (i < n) { a[i] = 0; b[i] = 0; }
}

__global__ void deg_kernel(const int* __restrict__ col, int* __restrict__ deg, int E) {
    int e = blockIdx.x * blockDim.x + threadIdx.x;
    if (e < E) atomicAdd(&deg[col[e]], 1);
}

__global__ void dinv_kernel(const int* __restrict__ deg, float* __restrict__ dinv, int n) {
    int i = blockIdx.x * blockDim.x + threadIdx.x;
    if (i < n) dinv[i] = 1.0f / sqrtf((float)(deg[i] + 1));  // +1 self loop
}

// single-block exclusive scan over deg -> offs, offs[n] = total
__global__ void scan_kernel(const int* __restrict__ deg, int* __restrict__ offs, int n) {
    __shared__ int buf[1024];
    __shared__ int carry;
    int t = threadIdx.x;
    if (t == 0) carry = 0;
    __syncthreads();
    for (int base = 0; base < n; base += 1024) {
        int i = base + t;
        int v = (i < n) ? deg[i] : 0;
        buf[t] = v;
        __syncthreads();
        for (int off = 1; off < 1024; off <<= 1) {
            int x = 0;
            if (t >= off) x = buf[t - off];
            __syncthreads();
            buf[t] += x;
            __syncthreads();
        }
        if (i < n) offs[i] = carry + buf[t] - v;
        __syncthreads();
        if (t == 0) carry += buf[1023];
        __syncthreads();
    }
    if (threadIdx.x == 0) offs[n] = carry;
}

__global__ void fill_kernel(const int* __restrict__ row, const int* __restrict__ col,
                            const float* __restrict__ dinv, const int* __restrict__ offs,
                            int* __restrict__ cursor, int* __restrict__ eidx,
                            float* __restrict__ norm, int E) {
    int e = blockIdx.x * blockDim.x + threadIdx.x;
    if (e >= E) return;
    int r = row[e], c = col[e];
    norm[e] = dinv[r] * dinv[c];
    int pos = offs[c] + atomicAdd(&cursor[c], 1);
    eidx[pos] = e;
}

// ---------------- tiled fp32 GEMM (128x64 tile, BK=16, fp32x2 acc) ----------
// C[M,N] = A[M,K] @ B[K,N] (+bias)(+relu). B row-stride = ldb.
template <int BIAS, int RELU>
__global__ __launch_bounds__(256) void gemm_k(
    const float* __restrict__ A, const float* __restrict__ B,
    const float* __restrict__ bias, float* __restrict__ C,
    int M, int K, int N, int ldb) {
    __shared__ float As[16][132];  // k-major, padded
    __shared__ float Bs[16][68];
    const int tid = threadIdx.x;
    const int tx = tid & 15;   // col group (4 cols)
    const int ty = tid >> 4;   // row group (8 rows)
    const int row0 = blockIdx.x * 128;
    const int col0 = blockIdx.y * 64;

    unsigned long long acc[4][4];
#pragma unroll
    for (int p = 0; p < 4; p++)
#pragma unroll
        for (int j = 0; j < 4; j++) acc[p][j] = 0ull;

    for (int kt = 0; kt < K; kt += 16) {
        // A tile: 128 rows x 16 k, transposed into As[k][m]
#pragma unroll
        for (int l = 0; l < 2; l++) {
            int f = tid + 256 * l;
            int r = f >> 2, c4 = f & 3;
            float4 v = make_float4(0.f, 0.f, 0.f, 0.f);
            int gr = row0 + r;
            if (gr < M) v = *(const float4*)(A + (size_t)gr * K + kt + c4 * 4);
            As[c4 * 4 + 0][r] = v.x;
            As[c4 * 4 + 1][r] = v.y;
            As[c4 * 4 + 2][r] = v.z;
            As[c4 * 4 + 3][r] = v.w;
        }
        // B tile: 16 k x 64 cols
        {
            int k = tid >> 4, c4 = tid & 15;
            float4 v = *(const float4*)(B + (size_t)(kt + k) * ldb + col0 + c4 * 4);
            *(float4*)&Bs[k][c4 * 4] = v;
        }
        __syncthreads();
#pragma unroll
        for (int k = 0; k < 16; k++) {
            unsigned long long a[4];
#pragma unroll
            for (int p = 0; p < 4; p++)
                a[p] = *(const unsigned long long*)&As[k][ty * 8 + p * 2];
            float4 bv = *(const float4*)&Bs[k][tx * 4];
            unsigned long long b0 = pk2(bv.x, bv.x), b1 = pk2(bv.y, bv.y);
            unsigned long long b2 = pk2(bv.z, bv.z), b3 = pk2(bv.w, bv.w);
#pragma unroll
            for (int p = 0; p < 4; p++) {
                fma2(acc[p][0], a[p], b0);
                fma2(acc[p][1], a[p], b1);
                fma2(acc[p][2], a[p], b2);
                fma2(acc[p][3], a[p], b3);
            }
        }
        __syncthreads();
    }
#pragma unroll
    for (int p = 0; p < 4; p++) {
        int gr0 = row0 + ty * 8 + p * 2;
#pragma unroll
        for (int j = 0; j < 4; j++) {
            int gc = col0 + tx * 4 + j;
            float2 v = up2(acc[p][j]);
            float bb = BIAS ? bias[gc] : 0.f;
            float x0 = v.x + bb, x1 = v.y + bb;
            if (RELU) { x0 = fmaxf(x0, 0.f); x1 = fmaxf(x1, 0.f); }
            if (gr0 < M) C[(size_t)gr0 * N + gc] = x0;
            if (gr0 + 1 < M) C[(size_t)(gr0 + 1) * N + gc] = x1;
        }
    }
}

// ---------------- GCN aggregation: one block per destination node -----------
// out[v] = relu( T[v]*dinv[v]^2 + sum_in T[row[e]]*norm[e] + bias )
__global__ void agg_kernel(const float* __restrict__ T, const float* __restrict__ bias,
                           float* __restrict__ outp, const int* __restrict__ offs,
                           const int* __restrict__ eidx, const int* __restrict__ rowArr,
                           const float* __restrict__ norm, const float* __restrict__ dinv,
                           int F) {
    int v = blockIdx.x;
    int j = threadIdx.x;
    float dv = dinv[v];
    float acc = T[(size_t)v * F + j] * dv * dv;
    int s = offs[v], e = offs[v + 1];
    for (int idx = s; idx < e; idx++) {
        int ed = eidx[idx];
        int r = rowArr[ed];
        acc += T[(size_t)r * F + j] * norm[ed];
    }
    outp[(size_t)v * F + j] = fmaxf(acc + bias[j], 0.f);
}

// ---------------- fused edge-MLP (persistent, 16 edges/group) ---------------
// hidden = relu(P[row] + Q[col] + attr @ We1[256:272] + be1); out = hidden @ We2 + be2
#define EPB 16
#define EDGE_SMEM_FLOATS (16 * 256 + 256 * 16 + EPB * 256 + EPB * 16 + 256 + 16 + 32)
__global__ __launch_bounds__(256) void edge_mlp_kernel(
    const float* __restrict__ P, const float* __restrict__ Q,
    const float* __restrict__ eattr, const int* __restrict__ rows,
    const int* __restrict__ cols, const float* __restrict__ We1b,
    const float* __restrict__ be1, const float* __restrict__ We2,
    const float* __restrict__ be2, float* __restrict__ out, int E) {
    extern __shared__ float sm[];
    float* sW1b = sm;                    // [16][256]  a*256+j
    float* sWe2 = sW1b + 16 * 256;       // [256][16]  j*16+a
    float* hid  = sWe2 + 256 * 16;       // [EPB][256]
    float* sattr = hid + EPB * 256;      // [EPB][16]
    float* sbe1 = sattr + EPB * 16;      // [256]
    float* sbe2 = sbe1 + 256;            // [16]
    int* sidx = (int*)(sbe2 + 16);       // row[16], col[16]

    int tid = threadIdx.x;
    for (int i = tid; i < 16 * 256; i += 256) sW1b[i] = We1b[i];
    for (int i = tid; i < 256 * 16; i += 256) sWe2[i] = We2[i];
    sbe1[tid] = be1[tid];
    if (tid < 16) sbe2[tid] = be2[tid];

    int ngroups = E / EPB;
    for (int g = blockIdx.x; g < ngroups; g += gridDim.x) {
        int e0 = g * EPB;
        sattr[tid] = eattr[(size_t)e0 * 16 + tid];  // 16 edges x 16 attrs
        if (tid < EPB) sidx[tid] = rows[e0 + tid];
        else if (tid < 2 * EPB) sidx[tid] = cols[e0 + tid - EPB];
        __syncthreads();

        // phase 1: thread = hidden column j, loop over 16 edges
        int j = tid;
        float vb = sbe1[j];
#pragma unroll 4
        for (int el = 0; el < EPB; el++) {
            int r = sidx[el], c = sidx[EPB + el];
            float v = P[(size_t)r * 256 + j] + Q[(size_t)c * 256 + j] + vb;
            const float* at = &sattr[el * 16];
#pragma unroll
            for (int a = 0; a < 16; a++) v = fmaf(at[a], sW1b[a * 256 + j], v);
            hid[el * 256 + j] = fmaxf(v, 0.f);
        }
        __syncthreads();

        // phase 2: thread = (edge, output) pair
        {
            int el = tid >> 4, a = tid & 15;
            float acc = sbe2[a];
            const float* h = &hid[el * 256];
#pragma unroll 16
            for (int jj = 0; jj < 256; jj++) acc = fmaf(h[jj], sWe2[jj * 16 + a], acc);
            out[(size_t)(e0 + el) * 16 + a] = acc;
        }
        __syncthreads();
    }
}

// ---------------- launch ------------------------------------------------------
extern "C" void kernel_launch(void* const* d_in, const int* in_sizes, int n_in,
                              void* d_out, int out_size) {
    const float* x    = (const float*)d_in[0];
    const int*   ei   = (const int*)d_in[1];
    const float* attr = (const float*)d_in[2];
    const float* W1  = (const float*)d_in[3];
    const float* b1  = (const float*)d_in[4];
    const float* W2  = (const float*)d_in[5];
    const float* b2  = (const float*)d_in[6];
    const float* Wo1 = (const float*)d_in[7];
    const float* bo1 = (const float*)d_in[8];
    const float* Wo2 = (const float*)d_in[9];
    const float* bo2 = (const float*)d_in[10];
    const float* We1 = (const float*)d_in[11];
    const float* be1 = (const float*)d_in[12];
    const float* We2 = (const float*)d_in[13];
    const float* be2 = (const float*)d_in[14];
    float* out = (float*)d_out;

    const int Nn = N_NODES, Ee = N_EDGES;
    const int* rowp = ei;
    const int* colp = ei + Ee;

    float *bufA, *bufB, *Pp, *Qp, *normp, *dinvp;
    int *degp, *offsp, *curp, *eidxp;
    cudaGetSymbolAddress((void**)&bufA, g_bufA);
    cudaGetSymbolAddress((void**)&bufB, g_bufB);
    cudaGetSymbolAddress((void**)&Pp, g_P);
    cudaGetSymbolAddress((void**)&Qp, g_Q);
    cudaGetSymbolAddress((void**)&normp, g_norm);
    cudaGetSymbolAddress((void**)&dinvp, g_dinv);
    cudaGetSymbolAddress((void**)&degp, g_deg);
    cudaGetSymbolAddress((void**)&offsp, g_offs);
    cudaGetSymbolAddress((void**)&curp, g_cursor);
    cudaGetSymbolAddress((void**)&eidxp, g_eidx);

    // --- graph prep: degrees, norms, CSR-by-destination
    zero2_kernel<<<(Nn + 255) / 256, 256>>>(degp, curp, Nn);
    deg_kernel<<<(Ee + 255) / 256, 256>>>(colp, degp, Ee);
    dinv_kernel<<<(Nn + 255) / 256, 256>>>(degp, dinvp, Nn);
    scan_kernel<<<1, 1024>>>(degp, offsp, Nn);
    fill_kernel<<<(Ee + 255) / 256, 256>>>(rowp, colp, dinvp, offsp, curp, eidxp,
                                           normp, Ee);

    dim3 blk(256);
    int gmx = (Nn + 127) / 128;

    // --- GCN layer 1: bufA = x@W1; bufB = relu(agg + b1)
    gemm_k<0, 0><<<dim3(gmx, DIM_H / 64), blk>>>(x, W1, nullptr, bufA, Nn, DIM_D, DIM_H, DIM_H);
    agg_kernel<<<Nn, DIM_H>>>(bufA, b1, bufB, offsp, eidxp, rowp, normp, dinvp, DIM_H);

    // --- GCN layer 2: bufA = h1@W2; bufB = relu(agg + b2)
    gemm_k<0, 0><<<dim3(gmx, DIM_D / 64), blk>>>(bufB, W2, nullptr, bufA, Nn, DIM_H, DIM_D, DIM_D);
    agg_kernel<<<Nn, DIM_D>>>(bufA, b2, bufB, offsp, eidxp, rowp, normp, dinvp, DIM_D);

    // --- output MLP: bufA = relu(h2@Wo1+bo1); out[node part] = bufA@Wo2 + bo2
    gemm_k<1, 1><<<dim3(gmx, DIM_H / 64), blk>>>(bufB, Wo1, bo1, bufA, Nn, DIM_D, DIM_H, DIM_H);
    gemm_k<1, 0><<<dim3(gmx, DIM_D / 64), blk>>>(bufA, Wo2, bo2, out, Nn, DIM_H, DIM_D, DIM_D);

    // --- edge predictor precompute: P = h@We1[0:128], Q = h@We1[128:256]
    gemm_k<0, 0><<<dim3(gmx, DIM_H / 64), blk>>>(out, We1, nullptr, Pp, Nn, DIM_D, DIM_H, DIM_H);
    gemm_k<0, 0><<<dim3(gmx, DIM_H / 64), blk>>>(out, We1 + 128 * DIM_H, nullptr, Qp, Nn,
                                                 DIM_D, DIM_H, DIM_H);

    // --- fused edge MLP
    int edge_smem = EDGE_SMEM_FLOATS * 4;
    cudaFuncSetAttribute(edge_mlp_kernel, cudaFuncAttributeMaxDynamicSharedMemorySize,
                         edge_smem);
    edge_mlp_kernel<<<1184, 256, edge_smem>>>(Pp, Qp, attr, rowp, colp,
                                              We1 + 256 * DIM_H, be1, We2, be2,
                                              out + (size_t)Nn * DIM_D, Ee);
}

// round 4
// speedup vs baseline: 1.5374x; 1.5374x over previous
#include <cuda_runtime.h>
#include <cuda_bf16.h>

#define N_NODES 50000
#define N_EDGES 800000
#define DIM_D   128
#define DIM_H   256
#define DIM_A   16

// ---------------- scratch (static device allocations; no cudaMalloc) --------
__device__ float g_bufA[N_NODES * DIM_H];
__device__ float g_bufB[N_NODES * DIM_H];
__device__ float g_P[N_NODES * DIM_H];
__device__ float g_Q[N_NODES * DIM_H];
__device__ float g_snorm[N_EDGES];   // norm sorted by destination
__device__ int   g_srcrow[N_EDGES];  // source row sorted by destination
__device__ float g_dinv[N_NODES];
__device__ int   g_deg[N_NODES];
__device__ int   g_offs[N_NODES + 1];
__device__ int   g_cursor[N_NODES];

// ---------------- fp32x2 packed helpers -------------------------------------
__device__ __forceinline__ unsigned long long pk2(float lo, float hi) {
    unsigned long long r;
    asm("mov.b64 %0, {%1,%2};" : "=l"(r) : "f"(lo), "f"(hi));
    return r;
}
__device__ __forceinline__ void fma2(unsigned long long& d, unsigned long long a,
                                     unsigned long long b) {
    asm("fma.rn.f32x2 %0, %1, %2, %3;" : "=l"(d) : "l"(a), "l"(b), "l"(d));
}
__device__ __forceinline__ float2 up2(unsigned long long v) {
    float lo, hi;
    asm("mov.b64 {%0,%1}, %2;" : "=f"(lo), "=f"(hi) : "l"(v));
    return make_float2(lo, hi);
}
__device__ __forceinline__ unsigned f2tf(float f) {
    unsigned r;
    asm("cvt.rna.tf32.f32 %0, %1;" : "=r"(r) : "f"(f));
    return r;
}
__device__ __forceinline__ void mma_tf32(float* c, const unsigned* a, const unsigned* b) {
    asm volatile(
        "mma.sync.aligned.m16n8k8.row.col.f32.tf32.tf32.f32 "
        "{%0,%1,%2,%3}, {%4,%5,%6,%7}, {%8,%9}, {%0,%1,%2,%3};"
        : "+f"(c[0]), "+f"(c[1]), "+f"(c[2]), "+f"(c[3])
        : "r"(a[0]), "r"(a[1]), "r"(a[2]), "r"(a[3]), "r"(b[0]), "r"(b[1]));
}

// ---------------- small prep kernels ----------------------------------------
__global__ void zero2_kernel(int* a, int* b, int n) {
    int i = blockIdx.x * blockDim.x + threadIdx.x;
    if (i < n) { a[i] = 0; b[i] = 0; }
}

__global__ void deg_kernel(const int* __restrict__ col, int* __restrict__ deg, int E) {
    int e = blockIdx.x * blockDim.x + threadIdx.x;
    if (e < E) atomicAdd(&deg[col[e]], 1);
}

__global__ void dinv_kernel(const int* __restrict__ deg, float* __restrict__ dinv, int n) {
    int i = blockIdx.x * blockDim.x + threadIdx.x;
    if (i < n) dinv[i] = 1.0f / sqrtf((float)(deg[i] + 1));  // +1 self loop
}

// single-block exclusive scan, shfl-based
__global__ void scan_kernel(const int* __restrict__ deg, int* __restrict__ offs, int n) {
    __shared__ int wexcl[32];
    __shared__ int stot;
    __shared__ int carry;
    int t = threadIdx.x, lane = t & 31, wid = t >> 5;
    if (t == 0) carry = 0;
    __syncthreads();
    for (int base = 0; base < n; base += 1024) {
        int i = base + t;
        int v = (i < n) ? deg[i] : 0;
        int s = v;
#pragma unroll
        for (int o = 1; o < 32; o <<= 1) {
            int x = __shfl_up_sync(0xffffffffu, s, o);
            if (lane >= o) s += x;
        }
        if (lane == 31) wexcl[wid] = s;
        __syncthreads();
        if (wid == 0) {
            int ws = wexcl[lane];
            int ss = ws;
#pragma unroll
            for (int o = 1; o < 32; o <<= 1) {
                int x = __shfl_up_sync(0xffffffffu, ss, o);
                if (lane >= o) ss += x;
            }
            wexcl[lane] = ss - ws;  // exclusive warp offsets
            if (lane == 31) stot = ss;
        }
        __syncthreads();
        if (i < n) offs[i] = carry + wexcl[wid] + s - v;
        __syncthreads();
        if (t == 0) carry += stot;
        __syncthreads();
    }
    if (t == 0) offs[n] = carry;
}

__global__ void fill_kernel(const int* __restrict__ row, const int* __restrict__ col,
                            const float* __restrict__ dinv, const int* __restrict__ offs,
                            int* __restrict__ cursor, int* __restrict__ srcrow,
                            float* __restrict__ snorm, int E) {
    int e = blockIdx.x * blockDim.x + threadIdx.x;
    if (e >= E) return;
    int r = row[e], c = col[e];
    int pos = offs[c] + atomicAdd(&cursor[c], 1);
    srcrow[pos] = r;
    snorm[pos] = dinv[r] * dinv[c];
}

// ---------------- tf32-split tensor-core GEMM --------------------------------
// C[M,N] = A[M,K] @ B[K,N] (+bias)(+relu). 128x64 block tile, BK=16.
// 2-term tf32 split (hi/lo), 3 mma passes => ~fp32 accuracy.
template <int BIAS, int RELU>
__global__ __launch_bounds__(256, 2) void mma_gemm(
    const float* __restrict__ A, const float* __restrict__ B,
    const float* __restrict__ bias, float* __restrict__ C,
    int M, int K, int N, int ldb) {
    __shared__ float As[128][20];   // [m][k], pad 4
    __shared__ float Bs[16][72];    // [k][n], pad 8
    const int tid = threadIdx.x, wid = tid >> 5, lane = tid & 31;
    const int gid = lane >> 2, tig = lane & 3;
    const int wm = (wid >> 1) * 32, wn = (wid & 1) * 32;
    const int row0 = blockIdx.x * 128, col0 = blockIdx.y * 64;

    float acc[2][4][4];
#pragma unroll
    for (int mt = 0; mt < 2; mt++)
#pragma unroll
        for (int nt = 0; nt < 4; nt++)
#pragma unroll
            for (int q = 0; q < 4; q++) acc[mt][nt][q] = 0.f;

    for (int kt = 0; kt < K; kt += 16) {
#pragma unroll
        for (int l = 0; l < 2; l++) {
            int f = tid + 256 * l;
            int r = f >> 2, c4 = (f & 3) * 4;
            int gr = row0 + r;
            float4 v = make_float4(0.f, 0.f, 0.f, 0.f);
            if (gr < M) v = *(const float4*)(A + (size_t)gr * K + kt + c4);
            As[r][c4] = v.x; As[r][c4 + 1] = v.y;
            As[r][c4 + 2] = v.z; As[r][c4 + 3] = v.w;
        }
        {
            int k = tid >> 4, c4 = (tid & 15) * 4;
            float4 v = *(const float4*)(B + (size_t)(kt + k) * ldb + col0 + c4);
            Bs[k][c4] = v.x; Bs[k][c4 + 1] = v.y;
            Bs[k][c4 + 2] = v.z; Bs[k][c4 + 3] = v.w;
        }
        __syncthreads();
#pragma unroll
        for (int ks = 0; ks < 16; ks += 8) {
            unsigned ah[2][4], al[2][4], bh[4][2], bl[4][2];
#pragma unroll
            for (int mt = 0; mt < 2; mt++) {
                int r0 = wm + mt * 16 + gid;
                float f0 = As[r0][ks + tig];
                float f1 = As[r0 + 8][ks + tig];
                float f2 = As[r0][ks + tig + 4];
                float f3 = As[r0 + 8][ks + tig + 4];
                ah[mt][0] = f2tf(f0); al[mt][0] = f2tf(f0 - __uint_as_float(ah[mt][0]));
                ah[mt][1] = f2tf(f1); al[mt][1] = f2tf(f1 - __uint_as_float(ah[mt][1]));
                ah[mt][2] = f2tf(f2); al[mt][2] = f2tf(f2 - __uint_as_float(ah[mt][2]));
                ah[mt][3] = f2tf(f3); al[mt][3] = f2tf(f3 - __uint_as_float(ah[mt][3]));
            }
#pragma unroll
            for (int nt = 0; nt < 4; nt++) {
                int c = wn + nt * 8 + gid;
                float g0 = Bs[ks + tig][c];
                float g1 = Bs[ks + tig + 4][c];
                bh[nt][0] = f2tf(g0); bl[nt][0] = f2tf(g0 - __uint_as_float(bh[nt][0]));
                bh[nt][1] = f2tf(g1); bl[nt][1] = f2tf(g1 - __uint_as_float(bh[nt][1]));
            }
#pragma unroll
            for (int mt = 0; mt < 2; mt++)
#pragma unroll
                for (int nt = 0; nt < 4; nt++) {
                    mma_tf32(acc[mt][nt], ah[mt], bh[nt]);
                    mma_tf32(acc[mt][nt], al[mt], bh[nt]);
                    mma_tf32(acc[mt][nt], ah[mt], bl[nt]);
                }
        }
        __syncthreads();
    }
#pragma unroll
    for (int mt = 0; mt < 2; mt++)
#pragma unroll
        for (int nt = 0; nt < 4; nt++) {
            int r = row0 + wm + mt * 16 + gid;
            int c = col0 + wn + nt * 8 + tig * 2;
            float b0 = BIAS ? bias[c] : 0.f;
            float b1 = BIAS ? bias[c + 1] : 0.f;
            float x0 = acc[mt][nt][0] + b0, x1 = acc[mt][nt][1] + b1;
            float x2 = acc[mt][nt][2] + b0, x3 = acc[mt][nt][3] + b1;
            if (RELU) {
                x0 = fmaxf(x0, 0.f); x1 = fmaxf(x1, 0.f);
                x2 = fmaxf(x2, 0.f); x3 = fmaxf(x3, 0.f);
            }
            if (r < M) { C[(size_t)r * N + c] = x0; C[(size_t)r * N + c + 1] = x1; }
            if (r + 8 < M) {
                C[(size_t)(r + 8) * N + c] = x2;
                C[(size_t)(r + 8) * N + c + 1] = x3;
            }
        }
}

// ---------------- GCN aggregation: one block per destination node -----------
__global__ void agg_kernel(const float* __restrict__ T, const float* __restrict__ bias,
                           float* __restrict__ outp, const int* __restrict__ offs,
                           const int* __restrict__ srcrow, const float* __restrict__ snorm,
                           const float* __restrict__ dinv, int F) {
    int v = blockIdx.x;
    int j = threadIdx.x;
    float dv = dinv[v];
    float acc = T[(size_t)v * F + j] * dv * dv;
    int s = offs[v], e = offs[v + 1];
    for (int idx = s; idx < e; idx++) {
        int r = srcrow[idx];
        acc += T[(size_t)r * F + j] * snorm[idx];
    }
    outp[(size_t)v * F + j] = fmaxf(acc + bias[j], 0.f);
}

// ---------------- fused edge-MLP (64 edges / block iteration) ----------------
// hidden = relu(P[row] + Q[col] + attr @ We1[256:272] + be1); out = hidden @ We2 + be2
#define EPB 64
#define HID_STRIDE 260
#define WT_STRIDE 260
// Wt + hid + sattr + sidx(128 ints)
#define EDGE_SMEM_FLOATS (16 * WT_STRIDE + EPB * HID_STRIDE + EPB * 16 + 128)
__global__ __launch_bounds__(256, 2) void edge_mlp_kernel(
    const float* __restrict__ P, const float* __restrict__ Q,
    const float* __restrict__ eattr, const int* __restrict__ rows,
    const int* __restrict__ cols, const float* __restrict__ We1b,
    const float* __restrict__ be1, const float* __restrict__ We2,
    const float* __restrict__ be2, float* __restrict__ out, int E) {
    extern __shared__ float sm[];
    float* Wt = sm;                         // [16][WT_STRIDE]  Wt[a][j] = We2[j][a]
    float* hid = Wt + 16 * WT_STRIDE;       // [EPB][HID_STRIDE]
    float* sattr = hid + EPB * HID_STRIDE;  // [EPB][16]
    int* sidx = (int*)(sattr + EPB * 16);   // rows[64], cols[64] -> 128 ints

    const int tid = threadIdx.x;
    const int j = tid;              // phase-1 hidden column
    const int elq = tid >> 4;       // phase-2 edge sub-index
    const int aa = tid & 15;        // phase-2 output column

    // We2 transposed into smem once
    for (int i = tid; i < 256 * 16; i += 256) {
        int jj = i >> 4, a = i & 15;
        Wt[a * WT_STRIDE + jj] = We2[i];
    }
    // phase-1 weights into registers (packed duplicated)
    unsigned long long w1d[16];
#pragma unroll
    for (int a = 0; a < 16; a++) {
        float w = We1b[a * 256 + j];
        w1d[a] = pk2(w, w);
    }
    const float vb = be1[j];
    const float rb2 = be2[aa];
    __syncthreads();

    const int ngroups = E / EPB;
    for (int g = blockIdx.x; g < ngroups; g += gridDim.x) {
        const int e0 = g * EPB;
        for (int i = tid; i < EPB * 16; i += 256) sattr[i] = eattr[(size_t)e0 * 16 + i];
        if (tid < EPB) sidx[tid] = rows[e0 + tid];
        else if (tid < 2 * EPB) sidx[tid] = cols[e0 + tid - EPB];
        __syncthreads();

        // phase 1: thread j, 32 edge-pairs packed in f32x2
#pragma unroll 2
        for (int p = 0; p < 32; p++) {
            int ea = 2 * p, eb = 2 * p + 1;
            int r0 = sidx[ea], r1 = sidx[eb];
            int c0 = sidx[EPB + ea], c1 = sidx[EPB + eb];
            float u0 = P[(size_t)r0 * 256 + j] + Q[(size_t)c0 * 256 + j] + vb;
            float u1 = P[(size_t)r1 * 256 + j] + Q[(size_t)c1 * 256 + j] + vb;
            unsigned long long v = pk2(u0, u1);
            unsigned long long v2 = 0ull;
            const float* a0p = &sattr[ea * 16];
            const float* a1p = &sattr[eb * 16];
#pragma unroll
            for (int a = 0; a < 16; a += 2) {
                fma2(v, pk2(a0p[a], a1p[a]), w1d[a]);
                fma2(v2, pk2(a0p[a + 1], a1p[a + 1]), w1d[a + 1]);
            }
            float2 f = up2(v), f2v = up2(v2);
            hid[ea * HID_STRIDE + j] = fmaxf(f.x + f2v.x, 0.f);
            hid[eb * HID_STRIDE + j] = fmaxf(f.y + f2v.y, 0.f);
        }
        __syncthreads();

        // phase 2: thread = (el, a); f32x2 dot products over 256 hidden
#pragma unroll
        for (int ebk = 0; ebk < 4; ebk++) {
            int el = ebk * 16 + elq;
            const float* h = &hid[el * HID_STRIDE];
            const float* w = &Wt[aa * WT_STRIDE];
            unsigned long long s0 = 0ull, s1 = 0ull;
#pragma unroll 8
            for (int jq = 0; jq < 256; jq += 4) {
                unsigned long long h01 = *(const unsigned long long*)&h[jq];
                unsigned long long h23 = *(const unsigned long long*)&h[jq + 2];
                unsigned long long w01 = *(const unsigned long long*)&w[jq];
                unsigned long long w23 = *(const unsigned long long*)&w[jq + 2];
                fma2(s0, h01, w01);
                fma2(s1, h23, w23);
            }
            float2 q0 = up2(s0), q1 = up2(s1);
            out[(size_t)(e0 + el) * 16 + aa] = q0.x + q0.y + q1.x + q1.y + rb2;
        }
        __syncthreads();
    }
}

// ---------------- launch ------------------------------------------------------
extern "C" void kernel_launch(void* const* d_in, const int* in_sizes, int n_in,
                              void* d_out, int out_size) {
    const float* x    = (const float*)d_in[0];
    const int*   ei   = (const int*)d_in[1];
    const float* attr = (const float*)d_in[2];
    const float* W1  = (const float*)d_in[3];
    const float* b1  = (const float*)d_in[4];
    const float* W2  = (const float*)d_in[5];
    const float* b2  = (const float*)d_in[6];
    const float* Wo1 = (const float*)d_in[7];
    const float* bo1 = (const float*)d_in[8];
    const float* Wo2 = (const float*)d_in[9];
    const float* bo2 = (const float*)d_in[10];
    const float* We1 = (const float*)d_in[11];
    const float* be1 = (const float*)d_in[12];
    const float* We2 = (const float*)d_in[13];
    const float* be2 = (const float*)d_in[14];
    float* out = (float*)d_out;

    const int Nn = N_NODES, Ee = N_EDGES;
    const int* rowp = ei;
    const int* colp = ei + Ee;

    float *bufA, *bufB, *Pp, *Qp, *snormp, *dinvp;
    int *degp, *offsp, *curp, *srcp;
    cudaGetSymbolAddress((void**)&bufA, g_bufA);
    cudaGetSymbolAddress((void**)&bufB, g_bufB);
    cudaGetSymbolAddress((void**)&Pp, g_P);
    cudaGetSymbolAddress((void**)&Qp, g_Q);
    cudaGetSymbolAddress((void**)&snormp, g_snorm);
    cudaGetSymbolAddress((void**)&dinvp, g_dinv);
    cudaGetSymbolAddress((void**)&degp, g_deg);
    cudaGetSymbolAddress((void**)&offsp, g_offs);
    cudaGetSymbolAddress((void**)&curp, g_cursor);
    cudaGetSymbolAddress((void**)&srcp, g_srcrow);

    // --- graph prep
    zero2_kernel<<<(Nn + 255) / 256, 256>>>(degp, curp, Nn);
    deg_kernel<<<(Ee + 255) / 256, 256>>>(colp, degp, Ee);
    dinv_kernel<<<(Nn + 255) / 256, 256>>>(degp, dinvp, Nn);
    scan_kernel<<<1, 1024>>>(degp, offsp, Nn);
    fill_kernel<<<(Ee + 255) / 256, 256>>>(rowp, colp, dinvp, offsp, curp, srcp,
                                           snormp, Ee);

    dim3 blk(256);
    int gmx = (Nn + 127) / 128;

    // --- GCN layer 1
    mma_gemm<0, 0><<<dim3(gmx, DIM_H / 64), blk>>>(x, W1, nullptr, bufA, Nn, DIM_D, DIM_H, DIM_H);
    agg_kernel<<<Nn, DIM_H>>>(bufA, b1, bufB, offsp, srcp, snormp, dinvp, DIM_H);

    // --- GCN layer 2
    mma_gemm<0, 0><<<dim3(gmx, DIM_D / 64), blk>>>(bufB, W2, nullptr, bufA, Nn, DIM_H, DIM_D, DIM_D);
    agg_kernel<<<Nn, DIM_D>>>(bufA, b2, bufB, offsp, srcp, snormp, dinvp, DIM_D);

    // --- output MLP
    mma_gemm<1, 1><<<dim3(gmx, DIM_H / 64), blk>>>(bufB, Wo1, bo1, bufA, Nn, DIM_D, DIM_H, DIM_H);
    mma_gemm<1, 0><<<dim3(gmx, DIM_D / 64), blk>>>(bufA, Wo2, bo2, out, Nn, DIM_H, DIM_D, DIM_D);

    // --- edge predictor precompute: P = h@We1[0:128], Q = h@We1[128:256]
    mma_gemm<0, 0><<<dim3(gmx, DIM_H / 64), blk>>>(out, We1, nullptr, Pp, Nn, DIM_D, DIM_H, DIM_H);
    mma_gemm<0, 0><<<dim3(gmx, DIM_H / 64), blk>>>(out, We1 + 128 * DIM_H, nullptr, Qp, Nn,
                                                   DIM_D, DIM_H, DIM_H);

    // --- fused edge MLP
    int edge_smem = EDGE_SMEM_FLOATS * 4;
    cudaFuncSetAttribute(edge_mlp_kernel, cudaFuncAttributeMaxDynamicSharedMemorySize,
                         edge_smem);
    edge_mlp_kernel<<<296, 256, edge_smem>>>(Pp, Qp, attr, rowp, colp,
                                             We1 + 256 * DIM_H, be1, We2, be2,
                                             out + (size_t)Nn * DIM_D, Ee);
}

// round 5
// speedup vs baseline: 1.9123x; 1.2438x over previous
#include <cuda_runtime.h>
#include <cuda_bf16.h>

#define N_NODES 50000
#define N_EDGES 800000
#define DIM_D   128
#define DIM_H   256
#define DIM_A   16

typedef __nv_bfloat16 bf16;

// ---------------- scratch (static device allocations) -----------------------
__device__ float g_bufA[N_NODES * DIM_H];          // GEMM -> agg intermediate
__device__ float g_P[N_NODES * DIM_H];
__device__ float g_Q[N_NODES * DIM_H];
__device__ bf16  g_shi0[N_NODES * DIM_H];          // split ping-pong buffers
__device__ bf16  g_slo0[N_NODES * DIM_H];
__device__ bf16  g_shi1[N_NODES * DIM_H];
__device__ bf16  g_slo1[N_NODES * DIM_H];
__device__ bf16  g_wbhi[7 * 65536];                // pre-split weights [n][k]
__device__ bf16  g_wblo[7 * 65536];
__device__ float g_snorm[N_EDGES];
__device__ int   g_srcrow[N_EDGES];
__device__ float g_dinv[N_NODES];
__device__ int   g_deg[N_NODES];
__device__ int   g_offs[N_NODES + 1];
__device__ int   g_cursor[N_NODES];
__device__ int   g_bsum[64];

// ---------------- packed helpers ---------------------------------------------
__device__ __forceinline__ unsigned long long pk2(float lo, float hi) {
    unsigned long long r;
    asm("mov.b64 %0, {%1,%2};" : "=l"(r) : "f"(lo), "f"(hi));
    return r;
}
__device__ __forceinline__ void fma2(unsigned long long& d, unsigned long long a,
                                     unsigned long long b) {
    asm("fma.rn.f32x2 %0, %1, %2, %3;" : "=l"(d) : "l"(a), "l"(b), "l"(d));
}
__device__ __forceinline__ float2 up2(unsigned long long v) {
    float lo, hi;
    asm("mov.b64 {%0,%1}, %2;" : "=f"(lo), "=f"(hi) : "l"(v));
    return make_float2(lo, hi);
}
// pack 2 floats -> bf16x2 (f0 in low half)
__device__ __forceinline__ unsigned bfpk(float f0, float f1) {
    unsigned r;
    asm("cvt.rn.bf16x2.f32 %0, %1, %2;" : "=r"(r) : "f"(f1), "f"(f0));
    return r;
}
__device__ __forceinline__ unsigned bfpk_lo(float f0, float f1, unsigned hp) {
    float h0 = __uint_as_float(hp << 16);
    float h1 = __uint_as_float(hp & 0xffff0000u);
    return bfpk(f0 - h0, f1 - h1);
}
__device__ __forceinline__ void mma_bf16(float* c, const unsigned* a, const unsigned* b) {
    asm volatile(
        "mma.sync.aligned.m16n8k16.row.col.f32.bf16.bf16.f32 "
        "{%0,%1,%2,%3}, {%4,%5,%6,%7}, {%8,%9}, {%0,%1,%2,%3};"
        : "+f"(c[0]), "+f"(c[1]), "+f"(c[2]), "+f"(c[3])
        : "r"(a[0]), "r"(a[1]), "r"(a[2]), "r"(a[3]), "r"(b[0]), "r"(b[1]));
}

// ---------------- prep kernels -----------------------------------------------
__global__ void zero2_kernel(int* a, int* b, int n) {
    int i = blockIdx.x * blockDim.x + threadIdx.x;
    if (i < n) { a[i] = 0; b[i] = 0; }
}
__global__ void deg_kernel(const int* __restrict__ col, int* __restrict__ deg, int E) {
    int e = blockIdx.x * blockDim.x + threadIdx.x;
    if (e < E) atomicAdd(&deg[col[e]], 1);
}
__global__ void dinv_kernel(const int* __restrict__ deg, float* __restrict__ dinv, int n) {
    int i = blockIdx.x * blockDim.x + threadIdx.x;
    if (i < n) dinv[i] = 1.0f / sqrtf((float)(deg[i] + 1));
}
// 3-phase scan
__global__ void scan1_kernel(const int* __restrict__ deg, int* __restrict__ offs,
                             int* __restrict__ bsum, int n) {
    __shared__ int wexcl[32];
    __shared__ int stot;
    int t = threadIdx.x, lane = t & 31, wid = t >> 5;
    int i = blockIdx.x * 1024 + t;
    int v = (i < n) ? deg[i] : 0;
    int s = v;
#pragma unroll
    for (int o = 1; o < 32; o <<= 1) {
        int x = __shfl_up_sync(0xffffffffu, s, o);
        if (lane >= o) s += x;
    }
    if (lane == 31) wexcl[wid] = s;
    __syncthreads();
    if (wid == 0) {
        int ws = wexcl[lane];
        int ss = ws;
#pragma unroll
        for (int o = 1; o < 32; o <<= 1) {
            int x = __shfl_up_sync(0xffffffffu, ss, o);
            if (lane >= o) ss += x;
        }
        wexcl[lane] = ss - ws;
        if (lane == 31) stot = ss;
    }
    __syncthreads();
    if (i < n) offs[i] = wexcl[wid] + s - v;
    if (t == 0) bsum[blockIdx.x] = stot;
}
__global__ void scan2_kernel(int* bsum, int* offs, int nb, int n) {
    if (threadIdx.x == 0) {
        int run = 0;
        for (int b = 0; b < nb; b++) { int t = bsum[b]; bsum[b] = run; run += t; }
        offs[n] = run;
    }
}
__global__ void scan3_kernel(int* offs, const int* bsum, int n) {
    int i = blockIdx.x * 1024 + threadIdx.x;
    if (i < n) offs[i] += bsum[i >> 10];
}
__global__ void fill_kernel(const int* __restrict__ row, const int* __restrict__ col,
                            const float* __restrict__ dinv, const int* __restrict__ offs,
                            int* __restrict__ cursor, int* __restrict__ srcrow,
                            float* __restrict__ snorm, int E) {
    int e = blockIdx.x * blockDim.x + threadIdx.x;
    if (e >= E) return;
    int r = row[e], c = col[e];
    int pos = offs[c] + atomicAdd(&cursor[c], 1);
    srcrow[pos] = r;
    snorm[pos] = dinv[r] * dinv[c];
}

// weight split+transpose: W fp32 [K][N] row-major -> whi/wlo bf16 [N][K]
__global__ void wcvt_kernel(const float* __restrict__ W, bf16* __restrict__ whi,
                            bf16* __restrict__ wlo, int K, int N) {
    int i = blockIdx.x * blockDim.x + threadIdx.x;
    if (i >= K * N) return;
    int k = i / N, n = i % N;
    float v = W[i];
    bf16 h = __float2bfloat16(v);
    whi[n * K + k] = h;
    wlo[n * K + k] = __float2bfloat16(v - __bfloat162float(h));
}
// elementwise split
__global__ void xcvt_kernel(const float* __restrict__ x, bf16* __restrict__ hi,
                            bf16* __restrict__ lo, int n) {
    int i = blockIdx.x * blockDim.x + threadIdx.x;
    if (i >= n) return;
    float v = x[i];
    bf16 h = __float2bfloat16(v);
    hi[i] = h;
    lo[i] = __float2bfloat16(v - __bfloat162float(h));
}

// ---------------- bf16-split tensor GEMM -------------------------------------
// C[M,N] = (Ahi+Alo)[M,K] @ (Whi+Wlo)^T ([N][K] storage). 128x64 tile, BK=32.
template <int BIAS, int RELU, int WF32, int WSPLIT>
__global__ __launch_bounds__(256, 2) void gemm_bf(
    const bf16* __restrict__ Ahi, const bf16* __restrict__ Alo,
    const bf16* __restrict__ Whi, const bf16* __restrict__ Wlo,
    const float* __restrict__ bias, float* __restrict__ Cf,
    bf16* __restrict__ Chi, bf16* __restrict__ Clo, int M, int K, int N) {
    __shared__ bf16 Ah[128 * 40], Al[128 * 40], Bh[64 * 40], Bl[64 * 40];
    const int tid = threadIdx.x, wid = tid >> 5, lane = tid & 31;
    const int gid = lane >> 2, tig = lane & 3;
    const int wm = (wid >> 1) * 32, wn = (wid & 1) * 32;
    const int row0 = blockIdx.x * 128, col0 = blockIdx.y * 64;

    float acc[2][4][4];
#pragma unroll
    for (int mt = 0; mt < 2; mt++)
#pragma unroll
        for (int nt = 0; nt < 4; nt++)
#pragma unroll
            for (int q = 0; q < 4; q++) acc[mt][nt][q] = 0.f;

    for (int kt = 0; kt < K; kt += 32) {
#pragma unroll
        for (int l = 0; l < 2; l++) {
            int f = tid + 256 * l;
            int r = f >> 2, c8 = (f & 3) * 8;
            int gr = row0 + r;
            uint4 vh = make_uint4(0, 0, 0, 0), vl = make_uint4(0, 0, 0, 0);
            if (gr < M) {
                vh = *(const uint4*)(Ahi + (size_t)gr * K + kt + c8);
                vl = *(const uint4*)(Alo + (size_t)gr * K + kt + c8);
            }
            *(uint4*)&Ah[r * 40 + c8] = vh;
            *(uint4*)&Al[r * 40 + c8] = vl;
        }
        {
            int nn = tid >> 2, c8 = (tid & 3) * 8;
            *(uint4*)&Bh[nn * 40 + c8] = *(const uint4*)(Whi + (size_t)(col0 + nn) * K + kt + c8);
            *(uint4*)&Bl[nn * 40 + c8] = *(const uint4*)(Wlo + (size_t)(col0 + nn) * K + kt + c8);
        }
        __syncthreads();
#pragma unroll
        for (int ks = 0; ks < 32; ks += 16) {
            unsigned ah[2][4], al[2][4], bh[4][2], bl[4][2];
#pragma unroll
            for (int mt = 0; mt < 2; mt++) {
                int r0 = wm + mt * 16 + gid;
                ah[mt][0] = *(const unsigned*)&Ah[r0 * 40 + ks + tig * 2];
                ah[mt][1] = *(const unsigned*)&Ah[(r0 + 8) * 40 + ks + tig * 2];
                ah[mt][2] = *(const unsigned*)&Ah[r0 * 40 + ks + tig * 2 + 8];
                ah[mt][3] = *(const unsigned*)&Ah[(r0 + 8) * 40 + ks + tig * 2 + 8];
                al[mt][0] = *(const unsigned*)&Al[r0 * 40 + ks + tig * 2];
                al[mt][1] = *(const unsigned*)&Al[(r0 + 8) * 40 + ks + tig * 2];
                al[mt][2] = *(const unsigned*)&Al[r0 * 40 + ks + tig * 2 + 8];
                al[mt][3] = *(const unsigned*)&Al[(r0 + 8) * 40 + ks + tig * 2 + 8];
            }
#pragma unroll
            for (int nt = 0; nt < 4; nt++) {
                int n0 = wn + nt * 8 + gid;
                bh[nt][0] = *(const unsigned*)&Bh[n0 * 40 + ks + tig * 2];
                bh[nt][1] = *(const unsigned*)&Bh[n0 * 40 + ks + tig * 2 + 8];
                bl[nt][0] = *(const unsigned*)&Bl[n0 * 40 + ks + tig * 2];
                bl[nt][1] = *(const unsigned*)&Bl[n0 * 40 + ks + tig * 2 + 8];
            }
#pragma unroll
            for (int mt = 0; mt < 2; mt++)
#pragma unroll
                for (int nt = 0; nt < 4; nt++) {
                    mma_bf16(acc[mt][nt], ah[mt], bh[nt]);
                    mma_bf16(acc[mt][nt], al[mt], bh[nt]);
                    mma_bf16(acc[mt][nt], ah[mt], bl[nt]);
                }
        }
        __syncthreads();
    }
#pragma unroll
    for (int mt = 0; mt < 2; mt++)
#pragma unroll
        for (int nt = 0; nt < 4; nt++) {
            int r = row0 + wm + mt * 16 + gid;
            int c = col0 + wn + nt * 8 + tig * 2;
            float b0 = BIAS ? bias[c] : 0.f;
            float b1 = BIAS ? bias[c + 1] : 0.f;
            float x0 = acc[mt][nt][0] + b0, x1 = acc[mt][nt][1] + b1;
            float x2 = acc[mt][nt][2] + b0, x3 = acc[mt][nt][3] + b1;
            if (RELU) {
                x0 = fmaxf(x0, 0.f); x1 = fmaxf(x1, 0.f);
                x2 = fmaxf(x2, 0.f); x3 = fmaxf(x3, 0.f);
            }
            if (r < M) {
                if (WF32) { Cf[(size_t)r * N + c] = x0; Cf[(size_t)r * N + c + 1] = x1; }
                if (WSPLIT) {
                    unsigned hp = bfpk(x0, x1);
                    ((unsigned*)Chi)[((size_t)r * N + c) >> 1] = hp;
                    ((unsigned*)Clo)[((size_t)r * N + c) >> 1] = bfpk_lo(x0, x1, hp);
                }
            }
            if (r + 8 < M) {
                if (WF32) {
                    Cf[(size_t)(r + 8) * N + c] = x2;
                    Cf[(size_t)(r + 8) * N + c + 1] = x3;
                }
                if (WSPLIT) {
                    unsigned hp = bfpk(x2, x3);
                    ((unsigned*)Chi)[((size_t)(r + 8) * N + c) >> 1] = hp;
                    ((unsigned*)Clo)[((size_t)(r + 8) * N + c) >> 1] = bfpk_lo(x2, x3, hp);
                }
            }
        }
}

// ---------------- GCN aggregation (writes split bf16 + relu) -----------------
__global__ void agg_kernel(const float* __restrict__ T, const float* __restrict__ bias,
                           bf16* __restrict__ shi, bf16* __restrict__ slo,
                           const int* __restrict__ offs, const int* __restrict__ srcrow,
                           const float* __restrict__ snorm, const float* __restrict__ dinv,
                           int F) {
    int v = blockIdx.x;
    int j = threadIdx.x;
    float dv = dinv[v];
    float acc = T[(size_t)v * F + j] * dv * dv;
    int s = offs[v], e = offs[v + 1];
    for (int idx = s; idx < e; idx++) {
        int r = srcrow[idx];
        acc += T[(size_t)r * F + j] * snorm[idx];
    }
    float val = fmaxf(acc + bias[j], 0.f);
    bf16 h = __float2bfloat16(val);
    shi[(size_t)v * F + j] = h;
    slo[(size_t)v * F + j] = __float2bfloat16(val - __bfloat162float(h));
}

// ---------------- fused edge-MLP: phase1 f32x2, phase2 bf16 MMA --------------
#define EPB 64
#define HS 264  // hid row stride (bf16 elems)
// smem bytes: W2 split 2*16*264*2 + hid split 2*64*264*2 + attr 64*16*4 + idx 128*4
#define EDGE_SMEM_BYTES (2 * 16 * HS * 2 + 2 * EPB * HS * 2 + EPB * 16 * 4 + 128 * 4)
__global__ __launch_bounds__(256, 2) void edge_mlp_kernel(
    const float* __restrict__ P, const float* __restrict__ Q,
    const float* __restrict__ eattr, const int* __restrict__ rows,
    const int* __restrict__ cols, const float* __restrict__ We1b,
    const float* __restrict__ be1, const bf16* __restrict__ W2hi,
    const bf16* __restrict__ W2lo, const float* __restrict__ be2,
    float* __restrict__ out, int E) {
    extern __shared__ char smraw[];
    bf16* sW2h = (bf16*)smraw;                    // [16][HS]
    bf16* sW2l = sW2h + 16 * HS;
    bf16* hidh = sW2l + 16 * HS;                  // [EPB][HS]
    bf16* hidl = hidh + EPB * HS;
    float* sattr = (float*)(hidl + EPB * HS);     // [EPB][16]
    int* sidx = (int*)(sattr + EPB * 16);         // rows[64], cols[64]

    const int tid = threadIdx.x;
    const int wid = tid >> 5, lane = tid & 31;
    const int gid = lane >> 2, tig = lane & 3;
    const int j = tid;

    // stage We2 split [16][256] -> smem
    for (int i = tid; i < 16 * 256; i += 256) {
        int n = i >> 8, k = i & 255;
        sW2h[n * HS + k] = W2hi[i];
        sW2l[n * HS + k] = W2lo[i];
    }
    // phase-1 attr weights in registers (fp32, duplicated pairs)
    unsigned long long w1d[16];
#pragma unroll
    for (int a = 0; a < 16; a++) {
        float w = We1b[a * 256 + j];
        w1d[a] = pk2(w, w);
    }
    const float vb = be1[j];
    __syncthreads();

    const int mt = wid >> 1;       // phase-2 m-tile (16 edges)
    const int nh = wid & 1;        // phase-2 n-half (8 outputs)
    const int ngroups = E / EPB;
    for (int g = blockIdx.x; g < ngroups; g += gridDim.x) {
        const int e0 = g * EPB;
        for (int i = tid; i < EPB * 16; i += 256) sattr[i] = eattr[(size_t)e0 * 16 + i];
        if (tid < EPB) sidx[tid] = rows[e0 + tid];
        else if (tid < 2 * EPB) sidx[tid] = cols[e0 + tid - EPB];
        __syncthreads();

        // phase 1: thread = hidden col j, 32 edge-pairs, f32x2; write split bf16
#pragma unroll 2
        for (int p = 0; p < 32; p++) {
            int ea = 2 * p, eb = 2 * p + 1;
            int r0 = sidx[ea], r1 = sidx[eb];
            int c0 = sidx[EPB + ea], c1 = sidx[EPB + eb];
            float u0 = P[(size_t)r0 * 256 + j] + Q[(size_t)c0 * 256 + j] + vb;
            float u1 = P[(size_t)r1 * 256 + j] + Q[(size_t)c1 * 256 + j] + vb;
            unsigned long long v = pk2(u0, u1);
            unsigned long long v2 = 0ull;
            const float* a0p = &sattr[ea * 16];
            const float* a1p = &sattr[eb * 16];
#pragma unroll
            for (int a = 0; a < 16; a += 2) {
                fma2(v, pk2(a0p[a], a1p[a]), w1d[a]);
                fma2(v2, pk2(a0p[a + 1], a1p[a + 1]), w1d[a + 1]);
            }
            float2 f = up2(v), f2v = up2(v2);
            float val0 = fmaxf(f.x + f2v.x, 0.f);
            float val1 = fmaxf(f.y + f2v.y, 0.f);
            bf16 h0 = __float2bfloat16(val0);
            bf16 h1 = __float2bfloat16(val1);
            hidh[ea * HS + j] = h0;
            hidl[ea * HS + j] = __float2bfloat16(val0 - __bfloat162float(h0));
            hidh[eb * HS + j] = h1;
            hidl[eb * HS + j] = __float2bfloat16(val1 - __bfloat162float(h1));
        }
        __syncthreads();

        // phase 2: per-warp m16n8k256 via 16x (m16n8k16, 3-pass split)
        {
            float c4[4] = {0.f, 0.f, 0.f, 0.f};
            const int m0 = mt * 16 + gid;
            const int n0 = nh * 8 + gid;
#pragma unroll
            for (int ks = 0; ks < 256; ks += 16) {
                unsigned ah[4], al[4], bh[2], bl[2];
                ah[0] = *(const unsigned*)&hidh[m0 * HS + ks + tig * 2];
                ah[1] = *(const unsigned*)&hidh[(m0 + 8) * HS + ks + tig * 2];
                ah[2] = *(const unsigned*)&hidh[m0 * HS + ks + tig * 2 + 8];
                ah[3] = *(const unsigned*)&hidh[(m0 + 8) * HS + ks + tig * 2 + 8];
                al[0] = *(const unsigned*)&hidl[m0 * HS + ks + tig * 2];
                al[1] = *(const unsigned*)&hidl[(m0 + 8) * HS + ks + tig * 2];
                al[2] = *(const unsigned*)&hidl[m0 * HS + ks + tig * 2 + 8];
                al[3] = *(const unsigned*)&hidl[(m0 + 8) * HS + ks + tig * 2 + 8];
                bh[0] = *(const unsigned*)&sW2h[n0 * HS + ks + tig * 2];
                bh[1] = *(const unsigned*)&sW2h[n0 * HS + ks + tig * 2 + 8];
                bl[0] = *(const unsigned*)&sW2l[n0 * HS + ks + tig * 2];
                bl[1] = *(const unsigned*)&sW2l[n0 * HS + ks + tig * 2 + 8];
                mma_bf16(c4, ah, bh);
                mma_bf16(c4, al, bh);
                mma_bf16(c4, ah, bl);
            }
            int col = nh * 8 + tig * 2;
            float b0 = be2[col], b1 = be2[col + 1];
            int er = e0 + mt * 16 + gid;
            out[(size_t)er * 16 + col] = c4[0] + b0;
            out[(size_t)er * 16 + col + 1] = c4[1] + b1;
            out[(size_t)(er + 8) * 16 + col] = c4[2] + b0;
            out[(size_t)(er + 8) * 16 + col + 1] = c4[3] + b1;
        }
        __syncthreads();
    }
}

// ---------------- launch ------------------------------------------------------
extern "C" void kernel_launch(void* const* d_in, const int* in_sizes, int n_in,
                              void* d_out, int out_size) {
    const float* x    = (const float*)d_in[0];
    const int*   ei   = (const int*)d_in[1];
    const float* attr = (const float*)d_in[2];
    const float* W1  = (const float*)d_in[3];
    const float* b1  = (const float*)d_in[4];
    const float* W2  = (const float*)d_in[5];
    const float* b2  = (const float*)d_in[6];
    const float* Wo1 = (const float*)d_in[7];
    const float* bo1 = (const float*)d_in[8];
    const float* Wo2 = (const float*)d_in[9];
    const float* bo2 = (const float*)d_in[10];
    const float* We1 = (const float*)d_in[11];
    const float* be1 = (const float*)d_in[12];
    const float* We2 = (const float*)d_in[13];
    const float* be2 = (const float*)d_in[14];
    float* out = (float*)d_out;

    const int Nn = N_NODES, Ee = N_EDGES;
    const int* rowp = ei;
    const int* colp = ei + Ee;

    float *bufA, *Pp, *Qp, *snormp, *dinvp;
    bf16 *shi0, *slo0, *shi1, *slo1, *wbhi, *wblo;
    int *degp, *offsp, *curp, *srcp, *bsump;
    cudaGetSymbolAddress((void**)&bufA, g_bufA);
    cudaGetSymbolAddress((void**)&Pp, g_P);
    cudaGetSymbolAddress((void**)&Qp, g_Q);
    cudaGetSymbolAddress((void**)&shi0, g_shi0);
    cudaGetSymbolAddress((void**)&slo0, g_slo0);
    cudaGetSymbolAddress((void**)&shi1, g_shi1);
    cudaGetSymbolAddress((void**)&slo1, g_slo1);
    cudaGetSymbolAddress((void**)&wbhi, g_wbhi);
    cudaGetSymbolAddress((void**)&wblo, g_wblo);
    cudaGetSymbolAddress((void**)&snormp, g_snorm);
    cudaGetSymbolAddress((void**)&dinvp, g_dinv);
    cudaGetSymbolAddress((void**)&degp, g_deg);
    cudaGetSymbolAddress((void**)&offsp, g_offs);
    cudaGetSymbolAddress((void**)&curp, g_cursor);
    cudaGetSymbolAddress((void**)&srcp, g_srcrow);
    cudaGetSymbolAddress((void**)&bsump, g_bsum);

    // --- graph prep
    zero2_kernel<<<(Nn + 255) / 256, 256>>>(degp, curp, Nn);
    deg_kernel<<<(Ee + 255) / 256, 256>>>(colp, degp, Ee);
    dinv_kernel<<<(Nn + 255) / 256, 256>>>(degp, dinvp, Nn);
    int nsb = (Nn + 1023) / 1024;
    scan1_kernel<<<nsb, 1024>>>(degp, offsp, bsump, Nn);
    scan2_kernel<<<1, 32>>>(bsump, offsp, nsb, Nn);
    scan3_kernel<<<nsb, 1024>>>(offsp, bsump, Nn);
    fill_kernel<<<(Ee + 255) / 256, 256>>>(rowp, colp, dinvp, offsp, curp, srcp,
                                           snormp, Ee);

    // --- weight splits (idx: 0=W1 1=W2 2=Wo1 3=Wo2 4=We1P 5=We1Q 6=We2)
    wcvt_kernel<<<128, 256>>>(W1, wbhi + 0 * 65536, wblo + 0 * 65536, 128, 256);
    wcvt_kernel<<<128, 256>>>(W2, wbhi + 1 * 65536, wblo + 1 * 65536, 256, 128);
    wcvt_kernel<<<128, 256>>>(Wo1, wbhi + 2 * 65536, wblo + 2 * 65536, 128, 256);
    wcvt_kernel<<<128, 256>>>(Wo2, wbhi + 3 * 65536, wblo + 3 * 65536, 256, 128);
    wcvt_kernel<<<128, 256>>>(We1, wbhi + 4 * 65536, wblo + 4 * 65536, 128, 256);
    wcvt_kernel<<<128, 256>>>(We1 + 128 * 256, wbhi + 5 * 65536, wblo + 5 * 65536, 128, 256);
    wcvt_kernel<<<16, 256>>>(We2, wbhi + 6 * 65536, wblo + 6 * 65536, 256, 16);

    // --- split input x
    xcvt_kernel<<<(Nn * 128 + 255) / 256, 256>>>(x, shi0, slo0, Nn * 128);

    dim3 blk(256);
    int gmx = (Nn + 127) / 128;

    // GCN layer 1: bufA = x@W1 ; agg -> S1 split
    gemm_bf<0, 0, 1, 0><<<dim3(gmx, 4), blk>>>(shi0, slo0, wbhi, wblo, nullptr,
                                               bufA, nullptr, nullptr, Nn, 128, 256);
    agg_kernel<<<Nn, 256>>>(bufA, b1, shi1, slo1, offsp, srcp, snormp, dinvp, 256);

    // GCN layer 2: bufA = h1@W2 ; agg -> S0 split
    gemm_bf<0, 0, 1, 0><<<dim3(gmx, 2), blk>>>(shi1, slo1, wbhi + 65536, wblo + 65536,
                                               nullptr, bufA, nullptr, nullptr, Nn, 256, 128);
    agg_kernel<<<Nn, 128>>>(bufA, b2, shi0, slo0, offsp, srcp, snormp, dinvp, 128);

    // output MLP: S1 = relu(h2@Wo1+bo1) split ; out = S1@Wo2+bo2 (f32 + S0 split)
    gemm_bf<1, 1, 0, 1><<<dim3(gmx, 4), blk>>>(shi0, slo0, wbhi + 2 * 65536,
                                               wblo + 2 * 65536, bo1, nullptr, shi1,
                                               slo1, Nn, 128, 256);
    gemm_bf<1, 0, 1, 1><<<dim3(gmx, 2), blk>>>(shi1, slo1, wbhi + 3 * 65536,
                                               wblo + 3 * 65536, bo2, out, shi0, slo0,
                                               Nn, 256, 128);

    // edge precompute: P = h@We1[0:128], Q = h@We1[128:256]
    gemm_bf<0, 0, 1, 0><<<dim3(gmx, 4), blk>>>(shi0, slo0, wbhi + 4 * 65536,
                                               wblo + 4 * 65536, nullptr, Pp, nullptr,
                                               nullptr, Nn, 128, 256);
    gemm_bf<0, 0, 1, 0><<<dim3(gmx, 4), blk>>>(shi0, slo0, wbhi + 5 * 65536,
                                               wblo + 5 * 65536, nullptr, Qp, nullptr,
                                               nullptr, Nn, 128, 256);

    // fused edge MLP
    cudaFuncSetAttribute(edge_mlp_kernel, cudaFuncAttributeMaxDynamicSharedMemorySize,
                         EDGE_SMEM_BYTES);
    edge_mlp_kernel<<<296, 256, EDGE_SMEM_BYTES>>>(Pp, Qp, attr, rowp, colp,
                                                   We1 + 256 * 256, be1,
                                                   wbhi + 6 * 65536, wblo + 6 * 65536,
                                                   be2, out + (size_t)Nn * 128, Ee);
}

// round 6
// speedup vs baseline: 1.9930x; 1.0422x over previous
#include <cuda_runtime.h>
#include <cuda_bf16.h>

#define N_NODES 50000
#define N_EDGES 800000
#define DIM_D   128
#define DIM_H   256
#define DIM_A   16

typedef __nv_bfloat16 bf16;

// ---------------- scratch (static device allocations) -----------------------
__device__ float g_bufA[N_NODES * DIM_H];
__device__ float g_P[N_NODES * DIM_H];
__device__ float g_Q[N_NODES * DIM_H];
__device__ bf16  g_shi0[N_NODES * DIM_H];
__device__ bf16  g_slo0[N_NODES * DIM_H];
__device__ bf16  g_shi1[N_NODES * DIM_H];
__device__ bf16  g_slo1[N_NODES * DIM_H];
__device__ bf16  g_wbhi[7 * 65536];
__device__ bf16  g_wblo[7 * 65536];
__device__ float g_snorm[N_EDGES];
__device__ int   g_srcrow[N_EDGES];
__device__ float g_dinv[N_NODES];
__device__ int   g_deg[N_NODES];
__device__ int   g_offs[N_NODES + 1];
__device__ int   g_cursor[N_NODES];
__device__ int   g_bsum[64];

// ---------------- packed helpers ---------------------------------------------
__device__ __forceinline__ unsigned long long pk2(float lo, float hi) {
    unsigned long long r;
    asm("mov.b64 %0, {%1,%2};" : "=l"(r) : "f"(lo), "f"(hi));
    return r;
}
__device__ __forceinline__ void fma2(unsigned long long& d, unsigned long long a,
                                     unsigned long long b) {
    asm("fma.rn.f32x2 %0, %1, %2, %3;" : "=l"(d) : "l"(a), "l"(b), "l"(d));
}
__device__ __forceinline__ float2 up2(unsigned long long v) {
    float lo, hi;
    asm("mov.b64 {%0,%1}, %2;" : "=f"(lo), "=f"(hi) : "l"(v));
    return make_float2(lo, hi);
}
__device__ __forceinline__ unsigned bfpk(float f0, float f1) {
    unsigned r;
    asm("cvt.rn.bf16x2.f32 %0, %1, %2;" : "=r"(r) : "f"(f1), "f"(f0));
    return r;
}
__device__ __forceinline__ unsigned bfpk_lo(float f0, float f1, unsigned hp) {
    float h0 = __uint_as_float(hp << 16);
    float h1 = __uint_as_float(hp & 0xffff0000u);
    return bfpk(f0 - h0, f1 - h1);
}
__device__ __forceinline__ void mma_bf16(float* c, const unsigned* a, const unsigned* b) {
    asm volatile(
        "mma.sync.aligned.m16n8k16.row.col.f32.bf16.bf16.f32 "
        "{%0,%1,%2,%3}, {%4,%5,%6,%7}, {%8,%9}, {%0,%1,%2,%3};"
        : "+f"(c[0]), "+f"(c[1]), "+f"(c[2]), "+f"(c[3])
        : "r"(a[0]), "r"(a[1]), "r"(a[2]), "r"(a[3]), "r"(b[0]), "r"(b[1]));
}
__device__ __forceinline__ void cpa16(unsigned smem, const void* g) {
    asm volatile("cp.async.ca.shared.global [%0], [%1], 16;" :: "r"(smem), "l"(g));
}

// ---------------- prep kernels -----------------------------------------------
__global__ void zero2_kernel(int* a, int* b, int n) {
    int i = blockIdx.x * blockDim.x + threadIdx.x;
    if (i < n) { a[i] = 0; b[i] = 0; }
}
__global__ void deg_kernel(const int* __restrict__ col, int* __restrict__ deg, int E) {
    int e = blockIdx.x * blockDim.x + threadIdx.x;
    if (e < E) atomicAdd(&deg[col[e]], 1);
}
__global__ void dinv_kernel(const int* __restrict__ deg, float* __restrict__ dinv, int n) {
    int i = blockIdx.x * blockDim.x + threadIdx.x;
    if (i < n) dinv[i] = 1.0f / sqrtf((float)(deg[i] + 1));
}
__global__ void scan1_kernel(const int* __restrict__ deg, int* __restrict__ offs,
                             int* __restrict__ bsum, int n) {
    __shared__ int wexcl[32];
    __shared__ int stot;
    int t = threadIdx.x, lane = t & 31, wid = t >> 5;
    int i = blockIdx.x * 1024 + t;
    int v = (i < n) ? deg[i] : 0;
    int s = v;
#pragma unroll
    for (int o = 1; o < 32; o <<= 1) {
        int x = __shfl_up_sync(0xffffffffu, s, o);
        if (lane >= o) s += x;
    }
    if (lane == 31) wexcl[wid] = s;
    __syncthreads();
    if (wid == 0) {
        int ws = wexcl[lane];
        int ss = ws;
#pragma unroll
        for (int o = 1; o < 32; o <<= 1) {
            int x = __shfl_up_sync(0xffffffffu, ss, o);
            if (lane >= o) ss += x;
        }
        wexcl[lane] = ss - ws;
        if (lane == 31) stot = ss;
    }
    __syncthreads();
    if (i < n) offs[i] = wexcl[wid] + s - v;
    if (t == 0) bsum[blockIdx.x] = stot;
}
__global__ void scan2_kernel(int* bsum, int* offs, int nb, int n) {
    if (threadIdx.x == 0) {
        int run = 0;
        for (int b = 0; b < nb; b++) { int t = bsum[b]; bsum[b] = run; run += t; }
        offs[n] = run;
    }
}
__global__ void scan3_kernel(int* offs, const int* bsum, int n) {
    int i = blockIdx.x * 1024 + threadIdx.x;
    if (i < n) offs[i] += bsum[i >> 10];
}
__global__ void fill_kernel(const int* __restrict__ row, const int* __restrict__ col,
                            const float* __restrict__ dinv, const int* __restrict__ offs,
                            int* __restrict__ cursor, int* __restrict__ srcrow,
                            float* __restrict__ snorm, int E) {
    int e = blockIdx.x * blockDim.x + threadIdx.x;
    if (e >= E) return;
    int r = row[e], c = col[e];
    int pos = offs[c] + atomicAdd(&cursor[c], 1);
    srcrow[pos] = r;
    snorm[pos] = dinv[r] * dinv[c];
}
__global__ void wcvt_kernel(const float* __restrict__ W, bf16* __restrict__ whi,
                            bf16* __restrict__ wlo, int K, int N) {
    int i = blockIdx.x * blockDim.x + threadIdx.x;
    if (i >= K * N) return;
    int k = i / N, n = i % N;
    float v = W[i];
    bf16 h = __float2bfloat16(v);
    whi[n * K + k] = h;
    wlo[n * K + k] = __float2bfloat16(v - __bfloat162float(h));
}
__global__ void xcvt_kernel(const float* __restrict__ x, bf16* __restrict__ hi,
                            bf16* __restrict__ lo, int n) {
    int i = blockIdx.x * blockDim.x + threadIdx.x;
    if (i >= n) return;
    float v = x[i];
    bf16 h = __float2bfloat16(v);
    hi[i] = h;
    lo[i] = __float2bfloat16(v - __bfloat162float(h));
}

// ---------------- bf16-split tensor GEMM, 2-stage cp.async pipeline ----------
// C[M,N] = (Ahi+Alo)[M,K] @ (Whi+Wlo)^T ([N][K] storage). 128x64 tile, BK=32.
// dyn smem elems: AH[2][5120] AL[2][5120] BH[2][2560] BL[2][2560]  (61440 B)
#define GEMM_SMEM_BYTES ((2 * 5120 * 2 + 2 * 2560 * 2) * 2)
template <int BIAS, int RELU, int WF32, int WSPLIT>
__global__ __launch_bounds__(256, 2) void gemm_bf(
    const bf16* __restrict__ Ahi, const bf16* __restrict__ Alo,
    const bf16* __restrict__ Whi, const bf16* __restrict__ Wlo,
    const float* __restrict__ bias, float* __restrict__ Cf,
    bf16* __restrict__ Chi, bf16* __restrict__ Clo, int M, int K, int N) {
    extern __shared__ bf16 dsm[];
    bf16* AH = dsm;               // [2][5120]
    bf16* AL = dsm + 10240;       // [2][5120]
    bf16* BH = dsm + 20480;       // [2][2560]
    bf16* BL = dsm + 25600;       // [2][2560]
    const unsigned smbase = (unsigned)__cvta_generic_to_shared(dsm);
    const int tid = threadIdx.x, wid = tid >> 5, lane = tid & 31;
    const int gid = lane >> 2, tig = lane & 3;
    const int wm = (wid >> 1) * 32, wn = (wid & 1) * 32;
    const int row0 = blockIdx.x * 128, col0 = blockIdx.y * 64;

    // load task precompute
    const int ar0 = tid >> 2, ach = (tid & 3) * 8;          // A: rows tid>>2 and +64
    const int br = tid >> 2, bch = ach;                      // B: 64 rows x 4 chunks
    const int agr0 = min(row0 + ar0, M - 1);
    const int agr1 = min(row0 + ar0 + 64, M - 1);

    float acc[2][4][4];
#pragma unroll
    for (int mt = 0; mt < 2; mt++)
#pragma unroll
        for (int nt = 0; nt < 4; nt++)
#pragma unroll
            for (int q = 0; q < 4; q++) acc[mt][nt][q] = 0.f;

    const int T = K >> 5;
#define LOAD_STAGE(kt, buf)                                                          \
    {                                                                                \
        unsigned aoff = smbase + (unsigned)((buf) * 5120 + ar0 * 40 + ach) * 2;      \
        cpa16(aoff, Ahi + (size_t)agr0 * K + (kt) + ach);                            \
        cpa16(aoff + 64 * 40 * 2, Ahi + (size_t)agr1 * K + (kt) + ach);              \
        cpa16(aoff + 10240 * 2, Alo + (size_t)agr0 * K + (kt) + ach);                \
        cpa16(aoff + (10240 + 64 * 40) * 2, Alo + (size_t)agr1 * K + (kt) + ach);    \
        unsigned boff = smbase + (unsigned)(20480 + (buf) * 2560 + br * 40 + bch) * 2; \
        cpa16(boff, Whi + (size_t)(col0 + br) * K + (kt) + bch);                     \
        cpa16(boff + 5120 * 2, Wlo + (size_t)(col0 + br) * K + (kt) + bch);          \
        asm volatile("cp.async.commit_group;");                                      \
    }

    LOAD_STAGE(0, 0)
    for (int t = 0; t < T; t++) {
        if (t + 1 < T) {
            LOAD_STAGE((t + 1) << 5, (t + 1) & 1)
            asm volatile("cp.async.wait_group 1;");
        } else {
            asm volatile("cp.async.wait_group 0;");
        }
        __syncthreads();
        const bf16* cAh = AH + (t & 1) * 5120;
        const bf16* cAl = AL + (t & 1) * 5120;
        const bf16* cBh = BH + (t & 1) * 2560;
        const bf16* cBl = BL + (t & 1) * 2560;
#pragma unroll
        for (int ks = 0; ks < 32; ks += 16) {
            unsigned ah[2][4], al[2][4], bh[4][2], bl[4][2];
#pragma unroll
            for (int mt = 0; mt < 2; mt++) {
                int r0 = wm + mt * 16 + gid;
                ah[mt][0] = *(const unsigned*)&cAh[r0 * 40 + ks + tig * 2];
                ah[mt][1] = *(const unsigned*)&cAh[(r0 + 8) * 40 + ks + tig * 2];
                ah[mt][2] = *(const unsigned*)&cAh[r0 * 40 + ks + tig * 2 + 8];
                ah[mt][3] = *(const unsigned*)&cAh[(r0 + 8) * 40 + ks + tig * 2 + 8];
                al[mt][0] = *(const unsigned*)&cAl[r0 * 40 + ks + tig * 2];
                al[mt][1] = *(const unsigned*)&cAl[(r0 + 8) * 40 + ks + tig * 2];
                al[mt][2] = *(const unsigned*)&cAl[r0 * 40 + ks + tig * 2 + 8];
                al[mt][3] = *(const unsigned*)&cAl[(r0 + 8) * 40 + ks + tig * 2 + 8];
            }
#pragma unroll
            for (int nt = 0; nt < 4; nt++) {
                int n0 = wn + nt * 8 + gid;
                bh[nt][0] = *(const unsigned*)&cBh[n0 * 40 + ks + tig * 2];
                bh[nt][1] = *(const unsigned*)&cBh[n0 * 40 + ks + tig * 2 + 8];
                bl[nt][0] = *(const unsigned*)&cBl[n0 * 40 + ks + tig * 2];
                bl[nt][1] = *(const unsigned*)&cBl[n0 * 40 + ks + tig * 2 + 8];
            }
#pragma unroll
            for (int mt = 0; mt < 2; mt++)
#pragma unroll
                for (int nt = 0; nt < 4; nt++) {
                    mma_bf16(acc[mt][nt], ah[mt], bh[nt]);
                    mma_bf16(acc[mt][nt], al[mt], bh[nt]);
                    mma_bf16(acc[mt][nt], ah[mt], bl[nt]);
                }
        }
        __syncthreads();
    }
#pragma unroll
    for (int mt = 0; mt < 2; mt++)
#pragma unroll
        for (int nt = 0; nt < 4; nt++) {
            int r = row0 + wm + mt * 16 + gid;
            int c = col0 + wn + nt * 8 + tig * 2;
            float b0 = BIAS ? bias[c] : 0.f;
            float b1 = BIAS ? bias[c + 1] : 0.f;
            float x0 = acc[mt][nt][0] + b0, x1 = acc[mt][nt][1] + b1;
            float x2 = acc[mt][nt][2] + b0, x3 = acc[mt][nt][3] + b1;
            if (RELU) {
                x0 = fmaxf(x0, 0.f); x1 = fmaxf(x1, 0.f);
                x2 = fmaxf(x2, 0.f); x3 = fmaxf(x3, 0.f);
            }
            if (r < M) {
                if (WF32) { Cf[(size_t)r * N + c] = x0; Cf[(size_t)r * N + c + 1] = x1; }
                if (WSPLIT) {
                    unsigned hp = bfpk(x0, x1);
                    ((unsigned*)Chi)[((size_t)r * N + c) >> 1] = hp;
                    ((unsigned*)Clo)[((size_t)r * N + c) >> 1] = bfpk_lo(x0, x1, hp);
                }
            }
            if (r + 8 < M) {
                if (WF32) {
                    Cf[(size_t)(r + 8) * N + c] = x2;
                    Cf[(size_t)(r + 8) * N + c + 1] = x3;
                }
                if (WSPLIT) {
                    unsigned hp = bfpk(x2, x3);
                    ((unsigned*)Chi)[((size_t)(r + 8) * N + c) >> 1] = hp;
                    ((unsigned*)Clo)[((size_t)(r + 8) * N + c) >> 1] = bfpk_lo(x2, x3, hp);
                }
            }
        }
}

// ---------------- GCN aggregation (writes split bf16 + relu) -----------------
__global__ void agg_kernel(const float* __restrict__ T, const float* __restrict__ bias,
                           bf16* __restrict__ shi, bf16* __restrict__ slo,
                           const int* __restrict__ offs, const int* __restrict__ srcrow,
                           const float* __restrict__ snorm, const float* __restrict__ dinv,
                           int F) {
    int v = blockIdx.x;
    int j = threadIdx.x;
    float dv = dinv[v];
    float acc = T[(size_t)v * F + j] * dv * dv;
    int s = offs[v], e = offs[v + 1];
    for (int idx = s; idx < e; idx++) {
        int r = srcrow[idx];
        acc += T[(size_t)r * F + j] * snorm[idx];
    }
    float val = fmaxf(acc + bias[j], 0.f);
    bf16 h = __float2bfloat16(val);
    shi[(size_t)v * F + j] = h;
    slo[(size_t)v * F + j] = __float2bfloat16(val - __bfloat162float(h));
}
// F=128 variant: 2 nodes per 256-thread block
__global__ void agg_kernel128(const float* __restrict__ T, const float* __restrict__ bias,
                              bf16* __restrict__ shi, bf16* __restrict__ slo,
                              const int* __restrict__ offs, const int* __restrict__ srcrow,
                              const float* __restrict__ snorm,
                              const float* __restrict__ dinv) {
    const int F = 128;
    int v = blockIdx.x * 2 + (threadIdx.x >> 7);
    int j = threadIdx.x & 127;
    float dv = dinv[v];
    float acc = T[(size_t)v * F + j] * dv * dv;
    int s = offs[v], e = offs[v + 1];
    for (int idx = s; idx < e; idx++) {
        int r = srcrow[idx];
        acc += T[(size_t)r * F + j] * snorm[idx];
    }
    float val = fmaxf(acc + bias[j], 0.f);
    bf16 h = __float2bfloat16(val);
    shi[(size_t)v * F + j] = h;
    slo[(size_t)v * F + j] = __float2bfloat16(val - __bfloat162float(h));
}

// ---------------- fused edge-MLP: phase1 f32x2, phase2 bf16 MMA --------------
#define EPB 64
#define HS 264
#define EDGE_SMEM_BYTES (2 * 16 * HS * 2 + 2 * EPB * HS * 2 + EPB * 16 * 4 + 128 * 4)
__global__ __launch_bounds__(256, 2) void edge_mlp_kernel(
    const float* __restrict__ P, const float* __restrict__ Q,
    const float* __restrict__ eattr, const int* __restrict__ rows,
    const int* __restrict__ cols, const float* __restrict__ We1b,
    const float* __restrict__ be1, const bf16* __restrict__ W2hi,
    const bf16* __restrict__ W2lo, const float* __restrict__ be2,
    float* __restrict__ out, int E) {
    extern __shared__ char smraw[];
    bf16* sW2h = (bf16*)smraw;
    bf16* sW2l = sW2h + 16 * HS;
    bf16* hidh = sW2l + 16 * HS;
    bf16* hidl = hidh + EPB * HS;
    float* sattr = (float*)(hidl + EPB * HS);
    int* sidx = (int*)(sattr + EPB * 16);

    const int tid = threadIdx.x;
    const int wid = tid >> 5, lane = tid & 31;
    const int gid = lane >> 2, tig = lane & 3;
    const int j = tid;

    for (int i = tid; i < 16 * 256; i += 256) {
        int n = i >> 8, k = i & 255;
        sW2h[n * HS + k] = W2hi[i];
        sW2l[n * HS + k] = W2lo[i];
    }
    unsigned long long w1d[16];
#pragma unroll
    for (int a = 0; a < 16; a++) {
        float w = We1b[a * 256 + j];
        w1d[a] = pk2(w, w);
    }
    const float vb = be1[j];
    __syncthreads();

    const int mt = wid >> 1;
    const int nh = wid & 1;
    const int ngroups = E / EPB;
    for (int g = blockIdx.x; g < ngroups; g += gridDim.x) {
        const int e0 = g * EPB;
        for (int i = tid; i < EPB * 16; i += 256) sattr[i] = eattr[(size_t)e0 * 16 + i];
        if (tid < EPB) sidx[tid] = rows[e0 + tid];
        else if (tid < 2 * EPB) sidx[tid] = cols[e0 + tid - EPB];
        __syncthreads();

#pragma unroll 4
        for (int p = 0; p < 32; p++) {
            int ea = 2 * p, eb = 2 * p + 1;
            int r0 = sidx[ea], r1 = sidx[eb];
            int c0 = sidx[EPB + ea], c1 = sidx[EPB + eb];
            float u0 = P[(size_t)r0 * 256 + j] + Q[(size_t)c0 * 256 + j] + vb;
            float u1 = P[(size_t)r1 * 256 + j] + Q[(size_t)c1 * 256 + j] + vb;
            unsigned long long v = pk2(u0, u1);
            unsigned long long v2 = 0ull;
            const float* a0p = &sattr[ea * 16];
            const float* a1p = &sattr[eb * 16];
#pragma unroll
            for (int a = 0; a < 16; a += 2) {
                fma2(v, pk2(a0p[a], a1p[a]), w1d[a]);
                fma2(v2, pk2(a0p[a + 1], a1p[a + 1]), w1d[a + 1]);
            }
            float2 f = up2(v), f2v = up2(v2);
            float val0 = fmaxf(f.x + f2v.x, 0.f);
            float val1 = fmaxf(f.y + f2v.y, 0.f);
            bf16 h0 = __float2bfloat16(val0);
            bf16 h1 = __float2bfloat16(val1);
            hidh[ea * HS + j] = h0;
            hidl[ea * HS + j] = __float2bfloat16(val0 - __bfloat162float(h0));
            hidh[eb * HS + j] = h1;
            hidl[eb * HS + j] = __float2bfloat16(val1 - __bfloat162float(h1));
        }
        __syncthreads();

        {
            float c4[4] = {0.f, 0.f, 0.f, 0.f};
            const int m0 = mt * 16 + gid;
            const int n0 = nh * 8 + gid;
#pragma unroll
            for (int ks = 0; ks < 256; ks += 16) {
                unsigned ah[4], al[4], bh[2], bl[2];
                ah[0] = *(const unsigned*)&hidh[m0 * HS + ks + tig * 2];
                ah[1] = *(const unsigned*)&hidh[(m0 + 8) * HS + ks + tig * 2];
                ah[2] = *(const unsigned*)&hidh[m0 * HS + ks + tig * 2 + 8];
                ah[3] = *(const unsigned*)&hidh[(m0 + 8) * HS + ks + tig * 2 + 8];
                al[0] = *(const unsigned*)&hidl[m0 * HS + ks + tig * 2];
                al[1] = *(const unsigned*)&hidl[(m0 + 8) * HS + ks + tig * 2];
                al[2] = *(const unsigned*)&hidl[m0 * HS + ks + tig * 2 + 8];
                al[3] = *(const unsigned*)&hidl[(m0 + 8) * HS + ks + tig * 2 + 8];
                bh[0] = *(const unsigned*)&sW2h[n0 * HS + ks + tig * 2];
                bh[1] = *(const unsigned*)&sW2h[n0 * HS + ks + tig * 2 + 8];
                bl[0] = *(const unsigned*)&sW2l[n0 * HS + ks + tig * 2];
                bl[1] = *(const unsigned*)&sW2l[n0 * HS + ks + tig * 2 + 8];
                mma_bf16(c4, ah, bh);
                mma_bf16(c4, al, bh);
                mma_bf16(c4, ah, bl);
            }
            int col = nh * 8 + tig * 2;
            float b0 = be2[col], b1 = be2[col + 1];
            int er = e0 + mt * 16 + gid;
            out[(size_t)er * 16 + col] = c4[0] + b0;
            out[(size_t)er * 16 + col + 1] = c4[1] + b1;
            out[(size_t)(er + 8) * 16 + col] = c4[2] + b0;
            out[(size_t)(er + 8) * 16 + col + 1] = c4[3] + b1;
        }
        __syncthreads();
    }
}

// ---------------- launch ------------------------------------------------------
extern "C" void kernel_launch(void* const* d_in, const int* in_sizes, int n_in,
                              void* d_out, int out_size) {
    const float* x    = (const float*)d_in[0];
    const int*   ei   = (const int*)d_in[1];
    const float* attr = (const float*)d_in[2];
    const float* W1  = (const float*)d_in[3];
    const float* b1  = (const float*)d_in[4];
    const float* W2  = (const float*)d_in[5];
    const float* b2  = (const float*)d_in[6];
    const float* Wo1 = (const float*)d_in[7];
    const float* bo1 = (const float*)d_in[8];
    const float* Wo2 = (const float*)d_in[9];
    const float* bo2 = (const float*)d_in[10];
    const float* We1 = (const float*)d_in[11];
    const float* be1 = (const float*)d_in[12];
    const float* We2 = (const float*)d_in[13];
    const float* be2 = (const float*)d_in[14];
    float* out = (float*)d_out;

    const int Nn = N_NODES, Ee = N_EDGES;
    const int* rowp = ei;
    const int* colp = ei + Ee;

    float *bufA, *Pp, *Qp, *snormp, *dinvp;
    bf16 *shi0, *slo0, *shi1, *slo1, *wbhi, *wblo;
    int *degp, *offsp, *curp, *srcp, *bsump;
    cudaGetSymbolAddress((void**)&bufA, g_bufA);
    cudaGetSymbolAddress((void**)&Pp, g_P);
    cudaGetSymbolAddress((void**)&Qp, g_Q);
    cudaGetSymbolAddress((void**)&shi0, g_shi0);
    cudaGetSymbolAddress((void**)&slo0, g_slo0);
    cudaGetSymbolAddress((void**)&shi1, g_shi1);
    cudaGetSymbolAddress((void**)&slo1, g_slo1);
    cudaGetSymbolAddress((void**)&wbhi, g_wbhi);
    cudaGetSymbolAddress((void**)&wblo, g_wblo);
    cudaGetSymbolAddress((void**)&snormp, g_snorm);
    cudaGetSymbolAddress((void**)&dinvp, g_dinv);
    cudaGetSymbolAddress((void**)&degp, g_deg);
    cudaGetSymbolAddress((void**)&offsp, g_offs);
    cudaGetSymbolAddress((void**)&curp, g_cursor);
    cudaGetSymbolAddress((void**)&srcp, g_srcrow);
    cudaGetSymbolAddress((void**)&bsump, g_bsum);

    cudaFuncSetAttribute(gemm_bf<0, 0, 1, 0>, cudaFuncAttributeMaxDynamicSharedMemorySize,
                         GEMM_SMEM_BYTES);
    cudaFuncSetAttribute(gemm_bf<1, 1, 0, 1>, cudaFuncAttributeMaxDynamicSharedMemorySize,
                         GEMM_SMEM_BYTES);
    cudaFuncSetAttribute(gemm_bf<1, 0, 1, 1>, cudaFuncAttributeMaxDynamicSharedMemorySize,
                         GEMM_SMEM_BYTES);
    cudaFuncSetAttribute(edge_mlp_kernel, cudaFuncAttributeMaxDynamicSharedMemorySize,
                         EDGE_SMEM_BYTES);

    dim3 blk(256);
    int gmx = (Nn + 127) / 128;

    // Launch order puts the first big GEMM in the profiled (4th) slot.
    xcvt_kernel<<<(Nn * 128 + 255) / 256, 256>>>(x, shi0, slo0, Nn * 128);          // 1
    wcvt_kernel<<<128, 256>>>(W1, wbhi + 0 * 65536, wblo + 0 * 65536, 128, 256);    // 2
    zero2_kernel<<<(Nn + 255) / 256, 256>>>(degp, curp, Nn);                        // 3
    gemm_bf<0, 0, 1, 0><<<dim3(gmx, 4), blk, GEMM_SMEM_BYTES>>>(                    // 4 (ncu)
        shi0, slo0, wbhi, wblo, nullptr, bufA, nullptr, nullptr, Nn, 128, 256);

    // graph prep
    deg_kernel<<<(Ee + 255) / 256, 256>>>(colp, degp, Ee);
    dinv_kernel<<<(Nn + 255) / 256, 256>>>(degp, dinvp, Nn);
    int nsb = (Nn + 1023) / 1024;
    scan1_kernel<<<nsb, 1024>>>(degp, offsp, bsump, Nn);
    scan2_kernel<<<1, 32>>>(bsump, offsp, nsb, Nn);
    scan3_kernel<<<nsb, 1024>>>(offsp, bsump, Nn);
    fill_kernel<<<(Ee + 255) / 256, 256>>>(rowp, colp, dinvp, offsp, curp, srcp,
                                           snormp, Ee);

    // remaining weight splits
    wcvt_kernel<<<128, 256>>>(W2, wbhi + 1 * 65536, wblo + 1 * 65536, 256, 128);
    wcvt_kernel<<<128, 256>>>(Wo1, wbhi + 2 * 65536, wblo + 2 * 65536, 128, 256);
    wcvt_kernel<<<128, 256>>>(Wo2, wbhi + 3 * 65536, wblo + 3 * 65536, 256, 128);
    wcvt_kernel<<<128, 256>>>(We1, wbhi + 4 * 65536, wblo + 4 * 65536, 128, 256);
    wcvt_kernel<<<128, 256>>>(We1 + 128 * 256, wbhi + 5 * 65536, wblo + 5 * 65536, 128, 256);
    wcvt_kernel<<<16, 256>>>(We2, wbhi + 6 * 65536, wblo + 6 * 65536, 256, 16);

    // GCN layer 1 agg
    agg_kernel<<<Nn, 256>>>(bufA, b1, shi1, slo1, offsp, srcp, snormp, dinvp, 256);

    // GCN layer 2
    gemm_bf<0, 0, 1, 0><<<dim3(gmx, 2), blk, GEMM_SMEM_BYTES>>>(
        shi1, slo1, wbhi + 65536, wblo + 65536, nullptr, bufA, nullptr, nullptr,
        Nn, 256, 128);
    agg_kernel128<<<Nn / 2, 256>>>(bufA, b2, shi0, slo0, offsp, srcp, snormp, dinvp);

    // output MLP
    gemm_bf<1, 1, 0, 1><<<dim3(gmx, 4), blk, GEMM_SMEM_BYTES>>>(
        shi0, slo0, wbhi + 2 * 65536, wblo + 2 * 65536, bo1, nullptr, shi1, slo1,
        Nn, 128, 256);
    gemm_bf<1, 0, 1, 1><<<dim3(gmx, 2), blk, GEMM_SMEM_BYTES>>>(
        shi1, slo1, wbhi + 3 * 65536, wblo + 3 * 65536, bo2, out, shi0, slo0,
        Nn, 256, 128);

    // edge precompute
    gemm_bf<0, 0, 1, 0><<<dim3(gmx, 4), blk, GEMM_SMEM_BYTES>>>(
        shi0, slo0, wbhi + 4 * 65536, wblo + 4 * 65536, nullptr, Pp, nullptr, nullptr,
        Nn, 128, 256);
    gemm_bf<0, 0, 1, 0><<<dim3(gmx, 4), blk, GEMM_SMEM_BYTES>>>(
        shi0, slo0, wbhi + 5 * 65536, wblo + 5 * 65536, nullptr, Qp, nullptr, nullptr,
        Nn, 128, 256);

    // fused edge MLP
    edge_mlp_kernel<<<296, 256, EDGE_SMEM_BYTES>>>(Pp, Qp, attr, rowp, colp,
                                                   We1 + 256 * 256, be1,
                                                   wbhi + 6 * 65536, wblo + 6 * 65536,
                                                   be2, out + (size_t)Nn * 128, Ee);
}

// round 7
// speedup vs baseline: 2.1484x; 1.0779x over previous
#include <cuda_runtime.h>
#include <cuda_bf16.h>

#define N_NODES 50000
#define N_EDGES 800000
#define DIM_D   128
#define DIM_H   256
#define DIM_A   16

typedef __nv_bfloat16 bf16;

// ---------------- scratch ----------------------------------------------------
__device__ float g_bufA[N_NODES * DIM_H];
__device__ float g_PQ[N_NODES * 512];
__device__ bf16  g_shi0[N_NODES * DIM_H];
__device__ bf16  g_slo0[N_NODES * DIM_H];
__device__ bf16  g_shi1[N_NODES * DIM_H];
__device__ bf16  g_slo1[N_NODES * DIM_H];
__device__ bf16  g_wbhi[7 * 65536];
__device__ bf16  g_wblo[7 * 65536];
__device__ float g_snorm[N_EDGES];
__device__ int   g_srcrow[N_EDGES];
__device__ float g_dinv[N_NODES];
__device__ int   g_deg[N_NODES];
__device__ int   g_offs[N_NODES + 1];
__device__ int   g_cursor[N_NODES];
__device__ int   g_bsum[64];

// ---------------- helpers ----------------------------------------------------
__device__ __forceinline__ unsigned long long pk2(float lo, float hi) {
    unsigned long long r;
    asm("mov.b64 %0, {%1,%2};" : "=l"(r) : "f"(lo), "f"(hi));
    return r;
}
__device__ __forceinline__ void fma2(unsigned long long& d, unsigned long long a,
                                     unsigned long long b) {
    asm("fma.rn.f32x2 %0, %1, %2, %3;" : "=l"(d) : "l"(a), "l"(b), "l"(d));
}
__device__ __forceinline__ float2 up2(unsigned long long v) {
    float lo, hi;
    asm("mov.b64 {%0,%1}, %2;" : "=f"(lo), "=f"(hi) : "l"(v));
    return make_float2(lo, hi);
}
__device__ __forceinline__ unsigned bfpk(float f0, float f1) {
    unsigned r;
    asm("cvt.rn.bf16x2.f32 %0, %1, %2;" : "=r"(r) : "f"(f1), "f"(f0));
    return r;
}
__device__ __forceinline__ unsigned bfpk_lo(float f0, float f1, unsigned hp) {
    float h0 = __uint_as_float(hp << 16);
    float h1 = __uint_as_float(hp & 0xffff0000u);
    return bfpk(f0 - h0, f1 - h1);
}
__device__ __forceinline__ void mma_bf16(float* c, const unsigned* a, const unsigned* b) {
    asm volatile(
        "mma.sync.aligned.m16n8k16.row.col.f32.bf16.bf16.f32 "
        "{%0,%1,%2,%3}, {%4,%5,%6,%7}, {%8,%9}, {%0,%1,%2,%3};"
        : "+f"(c[0]), "+f"(c[1]), "+f"(c[2]), "+f"(c[3])
        : "r"(a[0]), "r"(a[1]), "r"(a[2]), "r"(a[3]), "r"(b[0]), "r"(b[1]));
}
__device__ __forceinline__ void cpa16(unsigned smem, const void* g) {
    asm volatile("cp.async.ca.shared.global [%0], [%1], 16;" :: "r"(smem), "l"(g));
}
__device__ __forceinline__ void ldsm4(unsigned* r, unsigned saddr) {
    asm volatile("ldmatrix.sync.aligned.m8n8.x4.shared.b16 {%0,%1,%2,%3}, [%4];"
                 : "=r"(r[0]), "=r"(r[1]), "=r"(r[2]), "=r"(r[3]) : "r"(saddr));
}

// ---------------- prep kernels -----------------------------------------------
__global__ void zero2_kernel(int* a, int* b, int n) {
    int i = blockIdx.x * blockDim.x + threadIdx.x;
    if (i < n) { a[i] = 0; b[i] = 0; }
}
__global__ void deg_kernel(const int* __restrict__ col, int* __restrict__ deg, int E) {
    int e = blockIdx.x * blockDim.x + threadIdx.x;
    if (e < E) atomicAdd(&deg[col[e]], 1);
}
__global__ void dinv_kernel(const int* __restrict__ deg, float* __restrict__ dinv, int n) {
    int i = blockIdx.x * blockDim.x + threadIdx.x;
    if (i < n) dinv[i] = 1.0f / sqrtf((float)(deg[i] + 1));
}
__global__ void scan1_kernel(const int* __restrict__ deg, int* __restrict__ offs,
                             int* __restrict__ bsum, int n) {
    __shared__ int wexcl[32];
    __shared__ int stot;
    int t = threadIdx.x, lane = t & 31, wid = t >> 5;
    int i = blockIdx.x * 1024 + t;
    int v = (i < n) ? deg[i] : 0;
    int s = v;
#pragma unroll
    for (int o = 1; o < 32; o <<= 1) {
        int x = __shfl_up_sync(0xffffffffu, s, o);
        if (lane >= o) s += x;
    }
    if (lane == 31) wexcl[wid] = s;
    __syncthreads();
    if (wid == 0) {
        int ws = wexcl[lane];
        int ss = ws;
#pragma unroll
        for (int o = 1; o < 32; o <<= 1) {
            int x = __shfl_up_sync(0xffffffffu, ss, o);
            if (lane >= o) ss += x;
        }
        wexcl[lane] = ss - ws;
        if (lane == 31) stot = ss;
    }
    __syncthreads();
    if (i < n) offs[i] = wexcl[wid] + s - v;
    if (t == 0) bsum[blockIdx.x] = stot;
}
__global__ void scan2_kernel(int* bsum, int* offs, int nb, int n) {
    if (threadIdx.x == 0) {
        int run = 0;
        for (int b = 0; b < nb; b++) { int t = bsum[b]; bsum[b] = run; run += t; }
        offs[n] = run;
    }
}
__global__ void scan3_kernel(int* offs, const int* bsum, int n) {
    int i = blockIdx.x * 1024 + threadIdx.x;
    if (i < n) offs[i] += bsum[i >> 10];
}
__global__ void fill_kernel(const int* __restrict__ row, const int* __restrict__ col,
                            const float* __restrict__ dinv, const int* __restrict__ offs,
                            int* __restrict__ cursor, int* __restrict__ srcrow,
                            float* __restrict__ snorm, int E) {
    int e = blockIdx.x * blockDim.x + threadIdx.x;
    if (e >= E) return;
    int r = row[e], c = col[e];
    int pos = offs[c] + atomicAdd(&cursor[c], 1);
    srcrow[pos] = r;
    snorm[pos] = dinv[r] * dinv[c];
}
__global__ void wcvt_kernel(const float* __restrict__ W, bf16* __restrict__ whi,
                            bf16* __restrict__ wlo, int K, int N) {
    int i = blockIdx.x * blockDim.x + threadIdx.x;
    if (i >= K * N) return;
    int k = i / N, n = i % N;
    float v = W[i];
    bf16 h = __float2bfloat16(v);
    whi[n * K + k] = h;
    wlo[n * K + k] = __float2bfloat16(v - __bfloat162float(h));
}
__global__ void xcvt_kernel(const float* __restrict__ x, bf16* __restrict__ hi,
                            bf16* __restrict__ lo, int n) {
    int i = blockIdx.x * blockDim.x + threadIdx.x;
    if (i >= n) return;
    float v = x[i];
    bf16 h = __float2bfloat16(v);
    hi[i] = h;
    lo[i] = __float2bfloat16(v - __bfloat162float(h));
}

// ---------------- bf16-split tensor GEMM, cp.async + ldmatrix ----------------
#define GEMM_SMEM_BYTES ((2 * 5120 * 2 + 2 * 2560 * 2) * 2)
template <int BIAS, int RELU, int WF32, int WSPLIT>
__global__ __launch_bounds__(256, 2) void gemm_bf(
    const bf16* __restrict__ Ahi, const bf16* __restrict__ Alo,
    const bf16* __restrict__ Whi, const bf16* __restrict__ Wlo,
    const float* __restrict__ bias, float* __restrict__ Cf,
    bf16* __restrict__ Chi, bf16* __restrict__ Clo, int M, int K, int N) {
    extern __shared__ bf16 dsm[];
    const unsigned smbase = (unsigned)__cvta_generic_to_shared(dsm);
    const int tid = threadIdx.x, wid = tid >> 5, lane = tid & 31;
    const int gid = lane >> 2, tig = lane & 3;
    const int wm = (wid >> 1) * 32, wn = (wid & 1) * 32;
    const int row0 = blockIdx.x * 128, col0 = blockIdx.y * 64;

    const int ar0 = tid >> 2, ach = (tid & 3) * 8;
    const int br = tid >> 2, bch = ach;
    const int agr0 = min(row0 + ar0, M - 1);
    const int agr1 = min(row0 + ar0 + 64, M - 1);

    // ldmatrix per-lane address components
    const int aro = wm + (lane & 7) + ((lane >> 3) & 1) * 8;   // A row
    const int aco = (lane >> 4) * 8;                            // A col ofs
    const int bro = wn + (lane & 7) + (lane >> 4) * 8;          // B row (nt-pair)
    const int bco = ((lane >> 3) & 1) * 8;                      // B col ofs

    float acc[2][4][4];
#pragma unroll
    for (int mt = 0; mt < 2; mt++)
#pragma unroll
        for (int nt = 0; nt < 4; nt++)
#pragma unroll
            for (int q = 0; q < 4; q++) acc[mt][nt][q] = 0.f;

    const int T = K >> 5;
#define LOAD_STAGE(kt, buf)                                                          \
    {                                                                                \
        unsigned aoff = smbase + (unsigned)((buf) * 5120 + ar0 * 40 + ach) * 2;      \
        cpa16(aoff, Ahi + (size_t)agr0 * K + (kt) + ach);                            \
        cpa16(aoff + 64 * 40 * 2, Ahi + (size_t)agr1 * K + (kt) + ach);              \
        cpa16(aoff + 10240 * 2, Alo + (size_t)agr0 * K + (kt) + ach);                \
        cpa16(aoff + (10240 + 64 * 40) * 2, Alo + (size_t)agr1 * K + (kt) + ach);    \
        unsigned boff = smbase + (unsigned)(20480 + (buf) * 2560 + br * 40 + bch) * 2; \
        cpa16(boff, Whi + (size_t)(col0 + br) * K + (kt) + bch);                     \
        cpa16(boff + 5120 * 2, Wlo + (size_t)(col0 + br) * K + (kt) + bch);          \
        asm volatile("cp.async.commit_group;");                                      \
    }

    LOAD_STAGE(0, 0)
    for (int t = 0; t < T; t++) {
        if (t + 1 < T) {
            LOAD_STAGE((t + 1) << 5, (t + 1) & 1)
            asm volatile("cp.async.wait_group 1;");
        } else {
            asm volatile("cp.async.wait_group 0;");
        }
        __syncthreads();
        const unsigned abase = smbase + (unsigned)((t & 1) * 5120) * 2;
        const unsigned bbase = smbase + (unsigned)(20480 + (t & 1) * 2560) * 2;
#pragma unroll
        for (int ks = 0; ks < 32; ks += 16) {
            unsigned ah[2][4], al[2][4], bh[2][4], bl[2][4];
#pragma unroll
            for (int mt = 0; mt < 2; mt++) {
                unsigned adr = abase + (unsigned)((aro + mt * 16) * 40 + ks + aco) * 2;
                ldsm4(ah[mt], adr);
                ldsm4(al[mt], adr + 10240 * 2);
            }
#pragma unroll
            for (int np = 0; np < 2; np++) {
                unsigned bdr = bbase + (unsigned)((bro + np * 16) * 40 + ks + bco) * 2;
                ldsm4(bh[np], bdr);
                ldsm4(bl[np], bdr + 5120 * 2);
            }
#pragma unroll
            for (int mt = 0; mt < 2; mt++)
#pragma unroll
                for (int nt = 0; nt < 4; nt++) {
                    const unsigned* bhp = &bh[nt >> 1][(nt & 1) * 2];
                    const unsigned* blp = &bl[nt >> 1][(nt & 1) * 2];
                    mma_bf16(acc[mt][nt], ah[mt], bhp);
                    mma_bf16(acc[mt][nt], al[mt], bhp);
                    mma_bf16(acc[mt][nt], ah[mt], blp);
                }
        }
        __syncthreads();
    }
#pragma unroll
    for (int mt = 0; mt < 2; mt++)
#pragma unroll
        for (int nt = 0; nt < 4; nt++) {
            int r = row0 + wm + mt * 16 + gid;
            int c = col0 + wn + nt * 8 + tig * 2;
            float b0 = BIAS ? bias[c] : 0.f;
            float b1 = BIAS ? bias[c + 1] : 0.f;
            float x0 = acc[mt][nt][0] + b0, x1 = acc[mt][nt][1] + b1;
            float x2 = acc[mt][nt][2] + b0, x3 = acc[mt][nt][3] + b1;
            if (RELU) {
                x0 = fmaxf(x0, 0.f); x1 = fmaxf(x1, 0.f);
                x2 = fmaxf(x2, 0.f); x3 = fmaxf(x3, 0.f);
            }
            if (r < M) {
                if (WF32) { Cf[(size_t)r * N + c] = x0; Cf[(size_t)r * N + c + 1] = x1; }
                if (WSPLIT) {
                    unsigned hp = bfpk(x0, x1);
                    ((unsigned*)Chi)[((size_t)r * N + c) >> 1] = hp;
                    ((unsigned*)Clo)[((size_t)r * N + c) >> 1] = bfpk_lo(x0, x1, hp);
                }
            }
            if (r + 8 < M) {
                if (WF32) {
                    Cf[(size_t)(r + 8) * N + c] = x2;
                    Cf[(size_t)(r + 8) * N + c + 1] = x3;
                }
                if (WSPLIT) {
                    unsigned hp = bfpk(x2, x3);
                    ((unsigned*)Chi)[((size_t)(r + 8) * N + c) >> 1] = hp;
                    ((unsigned*)Clo)[((size_t)(r + 8) * N + c) >> 1] = bfpk_lo(x2, x3, hp);
                }
            }
        }
}

// ---------------- GCN aggregation --------------------------------------------
__global__ void agg_kernel(const float* __restrict__ T, const float* __restrict__ bias,
                           bf16* __restrict__ shi, bf16* __restrict__ slo,
                           const int* __restrict__ offs, const int* __restrict__ srcrow,
                           const float* __restrict__ snorm, const float* __restrict__ dinv,
                           int F) {
    int v = blockIdx.x;
    int j = threadIdx.x;
    float dv = dinv[v];
    float acc = T[(size_t)v * F + j] * dv * dv;
    int s = offs[v], e = offs[v + 1];
    for (int idx = s; idx < e; idx++) {
        int r = srcrow[idx];
        acc += T[(size_t)r * F + j] * snorm[idx];
    }
    float val = fmaxf(acc + bias[j], 0.f);
    bf16 h = __float2bfloat16(val);
    shi[(size_t)v * F + j] = h;
    slo[(size_t)v * F + j] = __float2bfloat16(val - __bfloat162float(h));
}
__global__ void agg_kernel128(const float* __restrict__ T, const float* __restrict__ bias,
                              bf16* __restrict__ shi, bf16* __restrict__ slo,
                              const int* __restrict__ offs, const int* __restrict__ srcrow,
                              const float* __restrict__ snorm,
                              const float* __restrict__ dinv) {
    const int F = 128;
    int v = blockIdx.x * 2 + (threadIdx.x >> 7);
    int j = threadIdx.x & 127;
    float dv = dinv[v];
    float acc = T[(size_t)v * F + j] * dv * dv;
    int s = offs[v], e = offs[v + 1];
    for (int idx = s; idx < e; idx++) {
        int r = srcrow[idx];
        acc += T[(size_t)r * F + j] * snorm[idx];
    }
    float val = fmaxf(acc + bias[j], 0.f);
    bf16 h = __float2bfloat16(val);
    shi[(size_t)v * F + j] = h;
    slo[(size_t)v * F + j] = __float2bfloat16(val - __bfloat162float(h));
}

// ---------------- fused edge-MLP ---------------------------------------------
#define EPB 64
#define HS 264
// W2 split + hid split + packed attr pairs (32x16 u64) + idx
#define EDGE_SMEM_BYTES (2 * 16 * HS * 2 + 2 * EPB * HS * 2 + 32 * 16 * 8 + 128 * 4)
__global__ __launch_bounds__(256, 2) void edge_mlp_kernel(
    const float* __restrict__ PQ,
    const float* __restrict__ eattr, const int* __restrict__ rows,
    const int* __restrict__ cols, const float* __restrict__ We1b,
    const float* __restrict__ be1, const bf16* __restrict__ W2hi,
    const bf16* __restrict__ W2lo, const float* __restrict__ be2,
    float* __restrict__ out, int E) {
    extern __shared__ char smraw[];
    bf16* sW2h = (bf16*)smraw;
    bf16* sW2l = sW2h + 16 * HS;
    bf16* hidh = sW2l + 16 * HS;
    bf16* hidl = hidh + EPB * HS;
    unsigned long long* sap = (unsigned long long*)(hidl + EPB * HS);  // [16][32]
    int* sidx = (int*)(sap + 16 * 32);

    const int tid = threadIdx.x;
    const int wid = tid >> 5, lane = tid & 31;
    const int gid = lane >> 2, tig = lane & 3;
    const int j = tid;

    for (int i = tid; i < 16 * 256; i += 256) {
        int n = i >> 8, k = i & 255;
        sW2h[n * HS + k] = W2hi[i];
        sW2l[n * HS + k] = W2lo[i];
    }
    unsigned long long w1d[16];
#pragma unroll
    for (int a = 0; a < 16; a++) {
        float w = We1b[a * 256 + j];
        w1d[a] = pk2(w, w);
    }
    const float vb = be1[j];
    __syncthreads();

    const int mt = wid >> 1;
    const int nh = wid & 1;
    const int ngroups = E / EPB;
    for (int g = blockIdx.x; g < ngroups; g += gridDim.x) {
        const int e0 = g * EPB;
        // packed attr pairs: sap[a][p] = (attr[2p][a], attr[2p+1][a])
#pragma unroll
        for (int i = tid; i < 512; i += 256) {
            int p = i & 31, a = i >> 5;
            sap[a * 32 + p] = pk2(eattr[(size_t)(e0 + 2 * p) * 16 + a],
                                  eattr[(size_t)(e0 + 2 * p + 1) * 16 + a]);
        }
        if (tid < EPB) sidx[tid] = rows[e0 + tid];
        else if (tid < 2 * EPB) sidx[tid] = cols[e0 + tid - EPB];
        __syncthreads();

#pragma unroll 4
        for (int p = 0; p < 32; p++) {
            int ea = 2 * p, eb = 2 * p + 1;
            int r0 = sidx[ea], r1 = sidx[eb];
            int c0 = sidx[EPB + ea], c1 = sidx[EPB + eb];
            float u0 = PQ[(size_t)r0 * 512 + j] + PQ[(size_t)c0 * 512 + 256 + j] + vb;
            float u1 = PQ[(size_t)r1 * 512 + j] + PQ[(size_t)c1 * 512 + 256 + j] + vb;
            unsigned long long v = pk2(u0, u1);
            unsigned long long v2 = 0ull;
#pragma unroll
            for (int a = 0; a < 16; a += 2) {
                fma2(v, sap[a * 32 + p], w1d[a]);
                fma2(v2, sap[(a + 1) * 32 + p], w1d[a + 1]);
            }
            float2 f = up2(v), f2v = up2(v2);
            float val0 = fmaxf(f.x + f2v.x, 0.f);
            float val1 = fmaxf(f.y + f2v.y, 0.f);
            bf16 h0 = __float2bfloat16(val0);
            bf16 h1 = __float2bfloat16(val1);
            hidh[ea * HS + j] = h0;
            hidl[ea * HS + j] = __float2bfloat16(val0 - __bfloat162float(h0));
            hidh[eb * HS + j] = h1;
            hidl[eb * HS + j] = __float2bfloat16(val1 - __bfloat162float(h1));
        }
        __syncthreads();

        {
            float c4[4] = {0.f, 0.f, 0.f, 0.f};
            const int m0 = mt * 16 + gid;
            const int n0 = nh * 8 + gid;
#pragma unroll
            for (int ks = 0; ks < 256; ks += 16) {
                unsigned ah[4], al[4], bh[2], bl[2];
                ah[0] = *(const unsigned*)&hidh[m0 * HS + ks + tig * 2];
                ah[1] = *(const unsigned*)&hidh[(m0 + 8) * HS + ks + tig * 2];
                ah[2] = *(const unsigned*)&hidh[m0 * HS + ks + tig * 2 + 8];
                ah[3] = *(const unsigned*)&hidh[(m0 + 8) * HS + ks + tig * 2 + 8];
                al[0] = *(const unsigned*)&hidl[m0 * HS + ks + tig * 2];
                al[1] = *(const unsigned*)&hidl[(m0 + 8) * HS + ks + tig * 2];
                al[2] = *(const unsigned*)&hidl[m0 * HS + ks + tig * 2 + 8];
                al[3] = *(const unsigned*)&hidl[(m0 + 8) * HS + ks + tig * 2 + 8];
                bh[0] = *(const unsigned*)&sW2h[n0 * HS + ks + tig * 2];
                bh[1] = *(const unsigned*)&sW2h[n0 * HS + ks + tig * 2 + 8];
                bl[0] = *(const unsigned*)&sW2l[n0 * HS + ks + tig * 2];
                bl[1] = *(const unsigned*)&sW2l[n0 * HS + ks + tig * 2 + 8];
                mma_bf16(c4, ah, bh);
                mma_bf16(c4, al, bh);
                mma_bf16(c4, ah, bl);
            }
            int col = nh * 8 + tig * 2;
            float b0 = be2[col], b1 = be2[col + 1];
            int er = e0 + mt * 16 + gid;
            out[(size_t)er * 16 + col] = c4[0] + b0;
            out[(size_t)er * 16 + col + 1] = c4[1] + b1;
            out[(size_t)(er + 8) * 16 + col] = c4[2] + b0;
            out[(size_t)(er + 8) * 16 + col + 1] = c4[3] + b1;
        }
        __syncthreads();
    }
}

// ---------------- launch ------------------------------------------------------
extern "C" void kernel_launch(void* const* d_in, const int* in_sizes, int n_in,
                              void* d_out, int out_size) {
    const float* x    = (const float*)d_in[0];
    const int*   ei   = (const int*)d_in[1];
    const float* attr = (const float*)d_in[2];
    const float* W1  = (const float*)d_in[3];
    const float* b1  = (const float*)d_in[4];
    const float* W2  = (const float*)d_in[5];
    const float* b2  = (const float*)d_in[6];
    const float* Wo1 = (const float*)d_in[7];
    const float* bo1 = (const float*)d_in[8];
    const float* Wo2 = (const float*)d_in[9];
    const float* bo2 = (const float*)d_in[10];
    const float* We1 = (const float*)d_in[11];
    const float* be1 = (const float*)d_in[12];
    const float* We2 = (const float*)d_in[13];
    const float* be2 = (const float*)d_in[14];
    float* out = (float*)d_out;

    const int Nn = N_NODES, Ee = N_EDGES;
    const int* rowp = ei;
    const int* colp = ei + Ee;

    float *bufA, *PQp, *snormp, *dinvp;
    bf16 *shi0, *slo0, *shi1, *slo1, *wbhi, *wblo;
    int *degp, *offsp, *curp, *srcp, *bsump;
    cudaGetSymbolAddress((void**)&bufA, g_bufA);
    cudaGetSymbolAddress((void**)&PQp, g_PQ);
    cudaGetSymbolAddress((void**)&shi0, g_shi0);
    cudaGetSymbolAddress((void**)&slo0, g_slo0);
    cudaGetSymbolAddress((void**)&shi1, g_shi1);
    cudaGetSymbolAddress((void**)&slo1, g_slo1);
    cudaGetSymbolAddress((void**)&wbhi, g_wbhi);
    cudaGetSymbolAddress((void**)&wblo, g_wblo);
    cudaGetSymbolAddress((void**)&snormp, g_snorm);
    cudaGetSymbolAddress((void**)&dinvp, g_dinv);
    cudaGetSymbolAddress((void**)&degp, g_deg);
    cudaGetSymbolAddress((void**)&offsp, g_offs);
    cudaGetSymbolAddress((void**)&curp, g_cursor);
    cudaGetSymbolAddress((void**)&srcp, g_srcrow);
    cudaGetSymbolAddress((void**)&bsump, g_bsum);

    cudaFuncSetAttribute(gemm_bf<0, 0, 1, 0>, cudaFuncAttributeMaxDynamicSharedMemorySize,
                         GEMM_SMEM_BYTES);
    cudaFuncSetAttribute(gemm_bf<1, 1, 0, 1>, cudaFuncAttributeMaxDynamicSharedMemorySize,
                         GEMM_SMEM_BYTES);
    cudaFuncSetAttribute(gemm_bf<1, 0, 1, 1>, cudaFuncAttributeMaxDynamicSharedMemorySize,
                         GEMM_SMEM_BYTES);
    cudaFuncSetAttribute(edge_mlp_kernel, cudaFuncAttributeMaxDynamicSharedMemorySize,
                         EDGE_SMEM_BYTES);

    dim3 blk(256);
    int gmx = (Nn + 127) / 128;

    // first big GEMM in the profiled (4th) slot
    xcvt_kernel<<<(Nn * 128 + 255) / 256, 256>>>(x, shi0, slo0, Nn * 128);          // 1
    wcvt_kernel<<<128, 256>>>(W1, wbhi + 0 * 65536, wblo + 0 * 65536, 128, 256);    // 2
    zero2_kernel<<<(Nn + 255) / 256, 256>>>(degp, curp, Nn);                        // 3
    gemm_bf<0, 0, 1, 0><<<dim3(gmx, 4), blk, GEMM_SMEM_BYTES>>>(                    // 4 (ncu)
        shi0, slo0, wbhi, wblo, nullptr, bufA, nullptr, nullptr, Nn, 128, 256);

    // graph prep
    deg_kernel<<<(Ee + 255) / 256, 256>>>(colp, degp, Ee);
    dinv_kernel<<<(Nn + 255) / 256, 256>>>(degp, dinvp, Nn);
    int nsb = (Nn + 1023) / 1024;
    scan1_kernel<<<nsb, 1024>>>(degp, offsp, bsump, Nn);
    scan2_kernel<<<1, 32>>>(bsump, offsp, nsb, Nn);
    scan3_kernel<<<nsb, 1024>>>(offsp, bsump, Nn);
    fill_kernel<<<(Ee + 255) / 256, 256>>>(rowp, colp, dinvp, offsp, curp, srcp,
                                           snormp, Ee);

    // remaining weight splits (PQ weights contiguous in slot 4: [512][128])
    wcvt_kernel<<<128, 256>>>(W2, wbhi + 1 * 65536, wblo + 1 * 65536, 256, 128);
    wcvt_kernel<<<128, 256>>>(Wo1, wbhi + 2 * 65536, wblo + 2 * 65536, 128, 256);
    wcvt_kernel<<<128, 256>>>(Wo2, wbhi + 3 * 65536, wblo + 3 * 65536, 256, 128);
    wcvt_kernel<<<128, 256>>>(We1, wbhi + 4 * 65536, wblo + 4 * 65536, 128, 256);
    wcvt_kernel<<<128, 256>>>(We1 + 128 * 256, wbhi + 4 * 65536 + 32768,
                              wblo + 4 * 65536 + 32768, 128, 256);
    wcvt_kernel<<<16, 256>>>(We2, wbhi + 6 * 65536, wblo + 6 * 65536, 256, 16);

    // GCN layer 1 agg
    agg_kernel<<<Nn, 256>>>(bufA, b1, shi1, slo1, offsp, srcp, snormp, dinvp, 256);

    // GCN layer 2
    gemm_bf<0, 0, 1, 0><<<dim3(gmx, 2), blk, GEMM_SMEM_BYTES>>>(
        shi1, slo1, wbhi + 65536, wblo + 65536, nullptr, bufA, nullptr, nullptr,
        Nn, 256, 128);
    agg_kernel128<<<Nn / 2, 256>>>(bufA, b2, shi0, slo0, offsp, srcp, snormp, dinvp);

    // output MLP
    gemm_bf<1, 1, 0, 1><<<dim3(gmx, 4), blk, GEMM_SMEM_BYTES>>>(
        shi0, slo0, wbhi + 2 * 65536, wblo + 2 * 65536, bo1, nullptr, shi1, slo1,
        Nn, 128, 256);
    gemm_bf<1, 0, 1, 1><<<dim3(gmx, 2), blk, GEMM_SMEM_BYTES>>>(
        shi1, slo1, wbhi + 3 * 65536, wblo + 3 * 65536, bo2, out, shi0, slo0,
        Nn, 256, 128);

    // fused PQ precompute: PQ = h @ [We1_P | We1_Q]  (N=512)
    gemm_bf<0, 0, 1, 0><<<dim3(gmx, 8), blk, GEMM_SMEM_BYTES>>>(
        shi0, slo0, wbhi + 4 * 65536, wblo + 4 * 65536, nullptr, PQp, nullptr, nullptr,
        Nn, 128, 512);

    // fused edge MLP
    edge_mlp_kernel<<<296, 256, EDGE_SMEM_BYTES>>>(PQp, attr, rowp, colp,
                                                   We1 + 256 * 256, be1,
                                                   wbhi + 6 * 65536, wblo + 6 * 65536,
                                                   be2, out + (size_t)Nn * 128, Ee);
}